// round 1
// baseline (speedup 1.0000x reference)
#include <cuda_runtime.h>
#include <math.h>

// ---------------------------------------------------------------------------
// Problem constants
// ---------------------------------------------------------------------------
constexpr int H    = 2048;
constexpr int NH   = 16;
constexpr int NOPE = 128;
constexpr int ROPE = 64;
constexpr int VD   = 128;
constexpr int QR   = 1024;
constexpr int KVR  = 512;
constexpr int BB   = 2;       // batch
constexpr int S    = 2048;    // seq len
constexpr int T    = BB * S;  // 4096 tokens
constexpr float EPS = 1e-6f;
constexpr float SM_SCALE = 0.07216878364870323f; // 1/sqrt(192)

// ---------------------------------------------------------------------------
// Device scratch (allocation-free rule: __device__ globals)
// ---------------------------------------------------------------------------
__device__ float g_cq   [T * QR];          //  16 MB
__device__ float g_qnope[T * NH * NOPE];   //  32 MB
__device__ float g_qrope[T * NH * ROPE];   //  16 MB
__device__ float g_ckv  [T * KVR];         //   8 MB
__device__ float g_knope[T * NH * NOPE];   //  32 MB
__device__ float g_v    [T * NH * VD];     //  32 MB
__device__ float g_krope[T * ROPE];        //   1 MB
__device__ float g_attn [T * NH * VD];     //  32 MB
__device__ float g_ctab [S * (ROPE / 2)];
__device__ float g_stab [S * (ROPE / 2)];

// ---------------------------------------------------------------------------
// Generic fp32 SGEMM: C[M,N] = A[M,K] @ B[K,N], row-major.
// 128x128 block tile, BK=16, 256 threads, 8x8 per thread.
// Requires: M % 128 == 0, K % 16 == 0, N % 4 == 0. (true for all calls here)
// ---------------------------------------------------------------------------
__global__ void __launch_bounds__(256)
sgemm_kernel(const float* __restrict__ A, const float* __restrict__ B,
             float* __restrict__ C, int M, int N, int K)
{
    __shared__ float As[16][128];
    __shared__ float Bs[16][128];

    const int tid = threadIdx.x;
    const int tx  = tid & 15;
    const int ty  = tid >> 4;
    const int rowBase = blockIdx.y * 128;
    const int colBase = blockIdx.x * 128;

    float acc[8][8];
#pragma unroll
    for (int i = 0; i < 8; i++)
#pragma unroll
        for (int j = 0; j < 8; j++) acc[i][j] = 0.f;

    for (int k0 = 0; k0 < K; k0 += 16) {
        // --- load A tile (128 x 16) via float4 along K ---
        {
            int i = tid;
#pragma unroll
            for (int it = 0; it < 2; it++, i += 256) {
                int m  = i >> 2;          // 0..127
                int kq = (i & 3) * 4;     // 0,4,8,12
                float4 a = *(const float4*)&A[(size_t)(rowBase + m) * K + k0 + kq];
                As[kq + 0][m] = a.x;
                As[kq + 1][m] = a.y;
                As[kq + 2][m] = a.z;
                As[kq + 3][m] = a.w;
            }
        }
        // --- load B tile (16 x 128) via float4 along N ---
        {
            int i = tid;
#pragma unroll
            for (int it = 0; it < 2; it++, i += 256) {
                int k  = i >> 5;          // 0..15
                int n4 = (i & 31) * 4;    // 0..124
                int gn = colBase + n4;
                float4 bv;
                if (gn < N) bv = *(const float4*)&B[(size_t)(k0 + k) * N + gn];
                else        bv = make_float4(0.f, 0.f, 0.f, 0.f);
                *(float4*)&Bs[k][n4] = bv;
            }
        }
        __syncthreads();

#pragma unroll
        for (int k = 0; k < 16; k++) {
            float4 a0 = *(const float4*)&As[k][ty * 8];
            float4 a1 = *(const float4*)&As[k][ty * 8 + 4];
            float4 b0 = *(const float4*)&Bs[k][tx * 8];
            float4 b1 = *(const float4*)&Bs[k][tx * 8 + 4];
            float av[8] = {a0.x, a0.y, a0.z, a0.w, a1.x, a1.y, a1.z, a1.w};
            float bv[8] = {b0.x, b0.y, b0.z, b0.w, b1.x, b1.y, b1.z, b1.w};
#pragma unroll
            for (int i = 0; i < 8; i++)
#pragma unroll
                for (int j = 0; j < 8; j++)
                    acc[i][j] += av[i] * bv[j];
        }
        __syncthreads();
    }

#pragma unroll
    for (int i = 0; i < 8; i++) {
        int gm = rowBase + ty * 8 + i;
#pragma unroll
        for (int j = 0; j < 8; j++) {
            int gn = colBase + tx * 8 + j;
            if (gn < N) C[(size_t)gm * N + gn] = acc[i][j];
        }
    }
}

// ---------------------------------------------------------------------------
// RMSNorm (in place): x[row, :D] *= rsqrt(mean(x^2)+eps) * scale[:D]
// one block per row
// ---------------------------------------------------------------------------
__global__ void rmsnorm_kernel(float* __restrict__ x,
                               const float* __restrict__ scale, int D)
{
    __shared__ float red[32];
    float* p = x + (size_t)blockIdx.x * D;

    float ss = 0.f;
    for (int d = threadIdx.x; d < D; d += blockDim.x) {
        float v = p[d];
        ss += v * v;
    }
#pragma unroll
    for (int o = 16; o; o >>= 1) ss += __shfl_xor_sync(0xffffffffu, ss, o);
    if ((threadIdx.x & 31) == 0) red[threadIdx.x >> 5] = ss;
    __syncthreads();
    if (threadIdx.x < 32) {
        float v = (threadIdx.x < (blockDim.x >> 5)) ? red[threadIdx.x] : 0.f;
#pragma unroll
        for (int o = 16; o; o >>= 1) v += __shfl_xor_sync(0xffffffffu, v, o);
        if (threadIdx.x == 0) red[0] = v;
    }
    __syncthreads();
    float inv = rsqrtf(red[0] / (float)D + EPS);
    for (int d = threadIdx.x; d < D; d += blockDim.x)
        p[d] = p[d] * inv * scale[d];
}

// ---------------------------------------------------------------------------
// RoPE cos/sin tables. Angle built in fp32 (to match reference rounding of
// pos*inv_freq), trig evaluated in fp64 (immune to fast-math degradation).
// ---------------------------------------------------------------------------
__global__ void rope_table_kernel(float* __restrict__ ctab, float* __restrict__ stab)
{
    int idx = blockIdx.x * blockDim.x + threadIdx.x;
    if (idx >= S * (ROPE / 2)) return;
    int i = idx % (ROPE / 2);
    int s = idx / (ROPE / 2);
    float freq = (float)pow(10000.0, -((double)(2 * i)) / (double)ROPE);
    float ang  = (float)s * freq;
    double a   = (double)ang;
    ctab[idx] = (float)cos(a);
    stab[idx] = (float)sin(a);
}

__global__ void rope_q_kernel(float* __restrict__ q,
                              const float* __restrict__ ctab,
                              const float* __restrict__ stab)
{
    int idx = blockIdx.x * blockDim.x + threadIdx.x;
    if (idx >= T * NH * (ROPE / 2)) return;
    int i   = idx & 31;
    int rem = idx >> 5;
    int h   = rem & (NH - 1);
    int tok = rem >> 4;
    int s   = tok & (S - 1);
    float c  = ctab[s * 32 + i];
    float sn = stab[s * 32 + i];
    float* p = q + (size_t)tok * (NH * ROPE) + h * ROPE + 2 * i;
    float x1 = p[0], x2 = p[1];
    p[0] = x1 * c - x2 * sn;
    p[1] = x1 * sn + x2 * c;
}

__global__ void rope_k_kernel(float* __restrict__ k,
                              const float* __restrict__ ctab,
                              const float* __restrict__ stab)
{
    int idx = blockIdx.x * blockDim.x + threadIdx.x;
    if (idx >= T * (ROPE / 2)) return;
    int i   = idx & 31;
    int tok = idx >> 5;
    int s   = tok & (S - 1);
    float c  = ctab[s * 32 + i];
    float sn = stab[s * 32 + i];
    float* p = k + (size_t)tok * ROPE + 2 * i;
    float x1 = p[0], x2 = p[1];
    p[0] = (x1 * c - x2 * sn) * 0.0625f;   // /NH folded in
    p[1] = (x1 * sn + x2 * c) * 0.0625f;
}

// ---------------------------------------------------------------------------
// Flash attention (fp32, causal). One block = one (b, h, 64-query tile).
// Scores over D=192 (nope||rope); V over 128. Online softmax, -1e9 mask
// on the diagonal tile exactly like the reference.
// ---------------------------------------------------------------------------
constexpr int BQ  = 64;
constexpr int BKT = 64;
constexpr int DQK = 192;

struct AttnSmem {
    float Q[BQ][196];      // padded stride (16B-aligned rows)
    float K[BKT][196];
    float V[BKT][132];
    float P[BQ][68];
    float alpha[BQ];
    float invl[BQ];
};

__global__ void __launch_bounds__(256)
attn_kernel(const float* __restrict__ qn, const float* __restrict__ qr,
            const float* __restrict__ kn, const float* __restrict__ kr,
            const float* __restrict__ v,  float* __restrict__ out)
{
    extern __shared__ char smraw[];
    AttnSmem& sm = *reinterpret_cast<AttnSmem*>(smraw);

    const int qt = blockIdx.x;
    const int h  = blockIdx.y;
    const int b  = blockIdx.z;
    const int tid = threadIdx.x;
    const int qb = b * S + qt * BQ;         // global token base for queries

    // ---- load Q tile: [64 x 192] ----
    for (int i = tid; i < BQ * NOPE; i += 256) {
        int r = i >> 7, d = i & 127;
        sm.Q[r][d] = qn[(size_t)(qb + r) * (NH * NOPE) + h * NOPE + d];
    }
    for (int i = tid; i < BQ * ROPE; i += 256) {
        int r = i >> 6, d = i & 63;
        sm.Q[r][128 + d] = qr[(size_t)(qb + r) * (NH * ROPE) + h * ROPE + d];
    }

    const int ty = tid >> 4, tx = tid & 15;   // score / PV mapping (16x16)
    const int srow = tid >> 2, squad = tid & 3; // softmax mapping (64 x 4)

    float m = -1e30f, l = 0.f;
    float acc[4][8];
#pragma unroll
    for (int i = 0; i < 4; i++)
#pragma unroll
        for (int j = 0; j < 8; j++) acc[i][j] = 0.f;

    const int nkt = qt + 1;                  // causal tile skip
    for (int kt = 0; kt < nkt; kt++) {
        const int kbT = b * S + kt * BKT;
        __syncthreads();   // previous iteration's PV reads are done

        // ---- load K tile [64 x 192] and V tile [64 x 128] ----
        for (int i = tid; i < BKT * NOPE; i += 256) {
            int r = i >> 7, d = i & 127;
            sm.K[r][d] = kn[(size_t)(kbT + r) * (NH * NOPE) + h * NOPE + d];
        }
        for (int i = tid; i < BKT * ROPE; i += 256) {
            int r = i >> 6, d = i & 63;
            sm.K[r][128 + d] = kr[(size_t)(kbT + r) * ROPE + d];
        }
        for (int i = tid; i < BKT * VD; i += 256) {
            int r = i >> 7, d = i & 127;
            sm.V[r][d] = v[(size_t)(kbT + r) * (NH * VD) + h * VD + d];
        }
        __syncthreads();

        // ---- scores: 4x4 per thread over D=192 ----
        float sacc[4][4];
#pragma unroll
        for (int i = 0; i < 4; i++)
#pragma unroll
            for (int j = 0; j < 4; j++) sacc[i][j] = 0.f;

#pragma unroll 4
        for (int d = 0; d < DQK; d += 4) {
            float4 qv[4], kv[4];
#pragma unroll
            for (int i = 0; i < 4; i++) qv[i] = *(const float4*)&sm.Q[ty * 4 + i][d];
#pragma unroll
            for (int j = 0; j < 4; j++) kv[j] = *(const float4*)&sm.K[tx * 4 + j][d];
#pragma unroll
            for (int i = 0; i < 4; i++)
#pragma unroll
                for (int j = 0; j < 4; j++)
                    sacc[i][j] += qv[i].x * kv[j].x + qv[i].y * kv[j].y
                                + qv[i].z * kv[j].z + qv[i].w * kv[j].w;
        }

        const bool diag = (kt == qt);
#pragma unroll
        for (int i = 0; i < 4; i++) {
            int qi = qt * BQ + ty * 4 + i;
#pragma unroll
            for (int j = 0; j < 4; j++) {
                int ki = kt * BKT + tx * 4 + j;
                float sv = sacc[i][j] * SM_SCALE;
                if (diag && ki > qi) sv = -1e9f;
                sm.P[ty * 4 + i][tx * 4 + j] = sv;
            }
        }
        __syncthreads();

        // ---- online softmax (per-row, quad of threads) ----
        {
            float sv[16];
            float tmax = -1e30f;
#pragma unroll
            for (int jj = 0; jj < 16; jj++) {
                sv[jj] = sm.P[srow][squad * 16 + jj];
                tmax = fmaxf(tmax, sv[jj]);
            }
            tmax = fmaxf(tmax, __shfl_xor_sync(0xffffffffu, tmax, 1));
            tmax = fmaxf(tmax, __shfl_xor_sync(0xffffffffu, tmax, 2));
            float mnew = fmaxf(m, tmax);
            float al   = expf(m - mnew);
            float ps = 0.f;
#pragma unroll
            for (int jj = 0; jj < 16; jj++) {
                float p = expf(sv[jj] - mnew);
                sm.P[srow][squad * 16 + jj] = p;
                ps += p;
            }
            ps += __shfl_xor_sync(0xffffffffu, ps, 1);
            ps += __shfl_xor_sync(0xffffffffu, ps, 2);
            l = l * al + ps;
            m = mnew;
            if (squad == 0) sm.alpha[srow] = al;
        }
        __syncthreads();

        // ---- O = O*alpha + P @ V ----
        {
            float al[4];
#pragma unroll
            for (int i = 0; i < 4; i++) al[i] = sm.alpha[ty * 4 + i];
#pragma unroll
            for (int i = 0; i < 4; i++)
#pragma unroll
                for (int j = 0; j < 8; j++) acc[i][j] *= al[i];

#pragma unroll 2
            for (int kj = 0; kj < BKT; kj++) {
                float4 v0 = *(const float4*)&sm.V[kj][tx * 8];
                float4 v1 = *(const float4*)&sm.V[kj][tx * 8 + 4];
                float pv[4];
#pragma unroll
                for (int i = 0; i < 4; i++) pv[i] = sm.P[ty * 4 + i][kj];
#pragma unroll
                for (int i = 0; i < 4; i++) {
                    acc[i][0] += pv[i] * v0.x;
                    acc[i][1] += pv[i] * v0.y;
                    acc[i][2] += pv[i] * v0.z;
                    acc[i][3] += pv[i] * v0.w;
                    acc[i][4] += pv[i] * v1.x;
                    acc[i][5] += pv[i] * v1.y;
                    acc[i][6] += pv[i] * v1.z;
                    acc[i][7] += pv[i] * v1.w;
                }
            }
        }
    }

    if (squad == 0) sm.invl[srow] = 1.f / l;
    __syncthreads();

#pragma unroll
    for (int i = 0; i < 4; i++) {
        float sc = sm.invl[ty * 4 + i];
        int tokq = qb + ty * 4 + i;
#pragma unroll
        for (int j = 0; j < 8; j++)
            out[(size_t)tokq * (NH * VD) + h * VD + tx * 8 + j] = acc[i][j] * sc;
    }
}

// ---------------------------------------------------------------------------
// Launch
// ---------------------------------------------------------------------------
static void launch_sgemm(const float* A, const float* B, float* C,
                         int M, int N, int K)
{
    dim3 grid((N + 127) / 128, (M + 127) / 128);
    sgemm_kernel<<<grid, 256>>>(A, B, C, M, N, K);
}

extern "C" void kernel_launch(void* const* d_in, const int* in_sizes, int n_in,
                              void* d_out, int out_size)
{
    const float* x         = (const float*)d_in[0];
    const float* W_cq      = (const float*)d_in[1];
    const float* q_scale   = (const float*)d_in[2];
    const float* W_dq_nope = (const float*)d_in[3];
    const float* W_dq_rope = (const float*)d_in[4];
    const float* W_ckv     = (const float*)d_in[5];
    const float* kv_scale  = (const float*)d_in[6];
    const float* W_dk_nope = (const float*)d_in[7];
    const float* W_dv      = (const float*)d_in[8];
    const float* W_krope   = (const float*)d_in[9];
    const float* W_o       = (const float*)d_in[10];
    float* out = (float*)d_out;

    float *cq, *qn, *qr, *ckv, *kn, *vv, *kr, *att, *ctab, *stab;
    cudaGetSymbolAddress((void**)&cq,  g_cq);
    cudaGetSymbolAddress((void**)&qn,  g_qnope);
    cudaGetSymbolAddress((void**)&qr,  g_qrope);
    cudaGetSymbolAddress((void**)&ckv, g_ckv);
    cudaGetSymbolAddress((void**)&kn,  g_knope);
    cudaGetSymbolAddress((void**)&vv,  g_v);
    cudaGetSymbolAddress((void**)&kr,  g_krope);
    cudaGetSymbolAddress((void**)&att, g_attn);
    cudaGetSymbolAddress((void**)&ctab, g_ctab);
    cudaGetSymbolAddress((void**)&stab, g_stab);

    // RoPE tables
    rope_table_kernel<<<(S * 32 + 255) / 256, 256>>>(ctab, stab);

    // Q path
    launch_sgemm(x, W_cq, cq, T, QR, H);
    rmsnorm_kernel<<<T, 256>>>(cq, q_scale, QR);
    launch_sgemm(cq, W_dq_nope, qn, T, NH * NOPE, QR);
    launch_sgemm(cq, W_dq_rope, qr, T, NH * ROPE, QR);
    rope_q_kernel<<<(T * NH * 32 + 255) / 256, 256>>>(qr, ctab, stab);

    // KV path
    launch_sgemm(x, W_ckv, ckv, T, KVR, H);
    rmsnorm_kernel<<<T, 256>>>(ckv, kv_scale, KVR);
    launch_sgemm(ckv, W_dk_nope, kn, T, NH * NOPE, KVR);
    launch_sgemm(ckv, W_dv, vv, T, NH * VD, KVR);
    launch_sgemm(x, W_krope, kr, T, ROPE, H);
    rope_k_kernel<<<(T * 32 + 255) / 256, 256>>>(kr, ctab, stab);

    // Attention
    cudaFuncSetAttribute((const void*)attn_kernel,
                         cudaFuncAttributeMaxDynamicSharedMemorySize,
                         (int)sizeof(AttnSmem));
    attn_kernel<<<dim3(S / BQ, NH, BB), 256, sizeof(AttnSmem)>>>(qn, qr, kn, kr, vv, att);

    // Output projection
    launch_sgemm(att, W_o, out, T, H, NH * VD);
}

// round 2
// speedup vs baseline: 1.4521x; 1.4521x over previous
#include <cuda_runtime.h>
#include <math.h>
#include <stdint.h>

// ---------------------------------------------------------------------------
// Problem constants
// ---------------------------------------------------------------------------
constexpr int H    = 2048;
constexpr int NH   = 16;
constexpr int NOPE = 128;
constexpr int ROPE = 64;
constexpr int VD   = 128;
constexpr int QR   = 1024;
constexpr int KVR  = 512;
constexpr int BB   = 2;       // batch
constexpr int S    = 2048;    // seq len
constexpr int T    = BB * S;  // 4096 tokens
constexpr float EPS = 1e-6f;
constexpr float SM_SCALE = 0.07216878364870323f; // 1/sqrt(192)

// ---------------------------------------------------------------------------
// Device scratch (allocation-free rule: __device__ globals)
// ---------------------------------------------------------------------------
__device__ float g_cq   [T * QR];          //  16 MB
__device__ float g_qnope[T * NH * NOPE];   //  32 MB
__device__ float g_qrope[T * NH * ROPE];   //  16 MB
__device__ float g_ckv  [T * KVR];         //   8 MB
__device__ float g_knope[T * NH * NOPE];   //  32 MB
__device__ float g_v    [T * NH * VD];     //  32 MB
__device__ float g_krope[T * ROPE];        //   1 MB
__device__ float g_attn [T * NH * VD];     //  32 MB
__device__ float g_ctab [S * (ROPE / 2)];
__device__ float g_stab [S * (ROPE / 2)];

// ---------------------------------------------------------------------------
// tf32 helpers
// ---------------------------------------------------------------------------
__device__ __forceinline__ float to_tf32(float x) {
    uint32_t u;
    asm("cvt.rna.tf32.f32 %0, %1;" : "=r"(u) : "f"(x));
    return __uint_as_float(u);
}
__device__ __forceinline__ float4 to_tf32x4(float4 v) {
    return make_float4(to_tf32(v.x), to_tf32(v.y), to_tf32(v.z), to_tf32(v.w));
}

__device__ __forceinline__ void mma_tf32(float& c0, float& c1, float& c2, float& c3,
                                         float a0, float a1, float a2, float a3,
                                         float b0, float b1)
{
    uint32_t ua0 = __float_as_uint(a0), ua1 = __float_as_uint(a1);
    uint32_t ua2 = __float_as_uint(a2), ua3 = __float_as_uint(a3);
    uint32_t ub0 = __float_as_uint(b0), ub1 = __float_as_uint(b1);
    asm volatile(
        "mma.sync.aligned.m16n8k8.row.col.f32.tf32.tf32.f32 "
        "{%0,%1,%2,%3}, {%4,%5,%6,%7}, {%8,%9}, {%0,%1,%2,%3};\n"
        : "+f"(c0), "+f"(c1), "+f"(c2), "+f"(c3)
        : "r"(ua0), "r"(ua1), "r"(ua2), "r"(ua3), "r"(ub0), "r"(ub1));
}

// ---------------------------------------------------------------------------
// tf32 tensor-core GEMM: C[M,N] = A[M,K] @ B[K,N], row-major fp32 in/out.
// 128x128 block tile, BK=16, 256 threads = 8 warps (2x4), warp tile 64x32.
// Double-buffered smem; padded strides for conflict-free fragment reads.
// Requires: M % 128 == 0, K % 16 == 0, N % 2 == 0.
// ---------------------------------------------------------------------------
constexpr int AS_STRIDE = 20;   // conflict-free for A-fragment reads
constexpr int BS_STRIDE = 136;  // conflict-free for B-fragment reads

__global__ void __launch_bounds__(256)
tf32_gemm_kernel(const float* __restrict__ A, const float* __restrict__ B,
                 float* __restrict__ C, int M, int N, int K)
{
    __shared__ float As[2][128][AS_STRIDE];
    __shared__ float Bs[2][16][BS_STRIDE];

    const int tid  = threadIdx.x;
    const int lane = tid & 31;
    const int warp = tid >> 5;
    const int qid  = lane >> 2;   // 0..7
    const int rid  = lane & 3;    // 0..3
    const int wr   = (warp >> 2) * 64;  // warp row base in tile
    const int wc   = (warp & 3) * 32;   // warp col base in tile

    const int rowBase = blockIdx.y * 128;
    const int colBase = blockIdx.x * 128;

    // global-load indices
    const int ar0 = tid >> 2;             // 0..63
    const int ar1 = ar0 + 64;             // 64..127
    const int ac  = (tid & 3) * 4;        // 0,4,8,12
    const int bk0 = tid >> 5;             // 0..7
    const int bk1 = bk0 + 8;              // 8..15
    const int bn  = (tid & 31) * 4;       // 0..124
    const int gn  = colBase + bn;
    const bool bok = (gn < N);

    float acc[4][4][4];
#pragma unroll
    for (int i = 0; i < 4; i++)
#pragma unroll
        for (int j = 0; j < 4; j++)
#pragma unroll
            for (int c = 0; c < 4; c++) acc[i][j][c] = 0.f;

    const int nt = K / 16;
    float4 ra0, ra1, rb0, rb1;

    // ---- prologue: tile 0 ----
    {
        ra0 = *(const float4*)&A[(size_t)(rowBase + ar0) * K + ac];
        ra1 = *(const float4*)&A[(size_t)(rowBase + ar1) * K + ac];
        rb0 = bok ? *(const float4*)&B[(size_t)bk0 * N + gn] : make_float4(0,0,0,0);
        rb1 = bok ? *(const float4*)&B[(size_t)bk1 * N + gn] : make_float4(0,0,0,0);
        *(float4*)&As[0][ar0][ac] = to_tf32x4(ra0);
        *(float4*)&As[0][ar1][ac] = to_tf32x4(ra1);
        *(float4*)&Bs[0][bk0][bn] = to_tf32x4(rb0);
        *(float4*)&Bs[0][bk1][bn] = to_tf32x4(rb1);
    }
    __syncthreads();

    for (int t = 0; t < nt; t++) {
        const int buf = t & 1;

        // prefetch next tile (global -> regs)
        if (t + 1 < nt) {
            const int k0 = (t + 1) * 16;
            ra0 = *(const float4*)&A[(size_t)(rowBase + ar0) * K + k0 + ac];
            ra1 = *(const float4*)&A[(size_t)(rowBase + ar1) * K + k0 + ac];
            rb0 = bok ? *(const float4*)&B[(size_t)(k0 + bk0) * N + gn] : make_float4(0,0,0,0);
            rb1 = bok ? *(const float4*)&B[(size_t)(k0 + bk1) * N + gn] : make_float4(0,0,0,0);
        }

        // compute on current buffer
#pragma unroll
        for (int ks = 0; ks < 16; ks += 8) {
            float a[4][4], b[4][2];
#pragma unroll
            for (int i = 0; i < 4; i++) {
                const float* p0 = &As[buf][wr + i * 16 + qid][ks + rid];
                const float* p1 = &As[buf][wr + i * 16 + qid + 8][ks + rid];
                a[i][0] = p0[0];
                a[i][1] = p1[0];
                a[i][2] = p0[4];
                a[i][3] = p1[4];
            }
#pragma unroll
            for (int j = 0; j < 4; j++) {
                b[j][0] = Bs[buf][ks + rid][wc + j * 8 + qid];
                b[j][1] = Bs[buf][ks + rid + 4][wc + j * 8 + qid];
            }
#pragma unroll
            for (int i = 0; i < 4; i++)
#pragma unroll
                for (int j = 0; j < 4; j++)
                    mma_tf32(acc[i][j][0], acc[i][j][1], acc[i][j][2], acc[i][j][3],
                             a[i][0], a[i][1], a[i][2], a[i][3],
                             b[j][0], b[j][1]);
        }

        // stage next tile into the other buffer
        if (t + 1 < nt) {
            const int nb = (t + 1) & 1;
            *(float4*)&As[nb][ar0][ac] = to_tf32x4(ra0);
            *(float4*)&As[nb][ar1][ac] = to_tf32x4(ra1);
            *(float4*)&Bs[nb][bk0][bn] = to_tf32x4(rb0);
            *(float4*)&Bs[nb][bk1][bn] = to_tf32x4(rb1);
        }
        __syncthreads();
    }

    // ---- epilogue ----
#pragma unroll
    for (int i = 0; i < 4; i++) {
        const int r0 = rowBase + wr + i * 16 + qid;
#pragma unroll
        for (int j = 0; j < 4; j++) {
            const int col = colBase + wc + j * 8 + rid * 2;
            if (col < N) {
                *(float2*)&C[(size_t)r0 * N + col]       = make_float2(acc[i][j][0], acc[i][j][1]);
                *(float2*)&C[(size_t)(r0 + 8) * N + col] = make_float2(acc[i][j][2], acc[i][j][3]);
            }
        }
    }
}

// ---------------------------------------------------------------------------
// RMSNorm (in place)
// ---------------------------------------------------------------------------
__global__ void rmsnorm_kernel(float* __restrict__ x,
                               const float* __restrict__ scale, int D)
{
    __shared__ float red[32];
    float* p = x + (size_t)blockIdx.x * D;

    float ss = 0.f;
    for (int d = threadIdx.x; d < D; d += blockDim.x) {
        float v = p[d];
        ss += v * v;
    }
#pragma unroll
    for (int o = 16; o; o >>= 1) ss += __shfl_xor_sync(0xffffffffu, ss, o);
    if ((threadIdx.x & 31) == 0) red[threadIdx.x >> 5] = ss;
    __syncthreads();
    if (threadIdx.x < 32) {
        float v = (threadIdx.x < (blockDim.x >> 5)) ? red[threadIdx.x] : 0.f;
#pragma unroll
        for (int o = 16; o; o >>= 1) v += __shfl_xor_sync(0xffffffffu, v, o);
        if (threadIdx.x == 0) red[0] = v;
    }
    __syncthreads();
    float inv = rsqrtf(red[0] / (float)D + EPS);
    for (int d = threadIdx.x; d < D; d += blockDim.x)
        p[d] = p[d] * inv * scale[d];
}

// ---------------------------------------------------------------------------
// RoPE tables / application
// ---------------------------------------------------------------------------
__global__ void rope_table_kernel(float* __restrict__ ctab, float* __restrict__ stab)
{
    int idx = blockIdx.x * blockDim.x + threadIdx.x;
    if (idx >= S * (ROPE / 2)) return;
    int i = idx % (ROPE / 2);
    int s = idx / (ROPE / 2);
    float freq = (float)pow(10000.0, -((double)(2 * i)) / (double)ROPE);
    float ang  = (float)s * freq;
    double a   = (double)ang;
    ctab[idx] = (float)cos(a);
    stab[idx] = (float)sin(a);
}

__global__ void rope_q_kernel(float* __restrict__ q,
                              const float* __restrict__ ctab,
                              const float* __restrict__ stab)
{
    int idx = blockIdx.x * blockDim.x + threadIdx.x;
    if (idx >= T * NH * (ROPE / 2)) return;
    int i   = idx & 31;
    int rem = idx >> 5;
    int h   = rem & (NH - 1);
    int tok = rem >> 4;
    int s   = tok & (S - 1);
    float c  = ctab[s * 32 + i];
    float sn = stab[s * 32 + i];
    float* p = q + (size_t)tok * (NH * ROPE) + h * ROPE + 2 * i;
    float x1 = p[0], x2 = p[1];
    p[0] = x1 * c - x2 * sn;
    p[1] = x1 * sn + x2 * c;
}

__global__ void rope_k_kernel(float* __restrict__ k,
                              const float* __restrict__ ctab,
                              const float* __restrict__ stab)
{
    int idx = blockIdx.x * blockDim.x + threadIdx.x;
    if (idx >= T * (ROPE / 2)) return;
    int i   = idx & 31;
    int tok = idx >> 5;
    int s   = tok & (S - 1);
    float c  = ctab[s * 32 + i];
    float sn = stab[s * 32 + i];
    float* p = k + (size_t)tok * ROPE + 2 * i;
    float x1 = p[0], x2 = p[1];
    p[0] = (x1 * c - x2 * sn) * 0.0625f;   // /NH folded in
    p[1] = (x1 * sn + x2 * c) * 0.0625f;
}

// ---------------------------------------------------------------------------
// Flash attention (fp32, causal) — unchanged from round 1
// ---------------------------------------------------------------------------
constexpr int BQ  = 64;
constexpr int BKT = 64;
constexpr int DQK = 192;

struct AttnSmem {
    float Q[BQ][196];
    float K[BKT][196];
    float V[BKT][132];
    float P[BQ][68];
    float alpha[BQ];
    float invl[BQ];
};

__global__ void __launch_bounds__(256)
attn_kernel(const float* __restrict__ qn, const float* __restrict__ qr,
            const float* __restrict__ kn, const float* __restrict__ kr,
            const float* __restrict__ v,  float* __restrict__ out)
{
    extern __shared__ char smraw[];
    AttnSmem& sm = *reinterpret_cast<AttnSmem*>(smraw);

    const int qt = blockIdx.x;
    const int h  = blockIdx.y;
    const int b  = blockIdx.z;
    const int tid = threadIdx.x;
    const int qb = b * S + qt * BQ;

    for (int i = tid; i < BQ * NOPE; i += 256) {
        int r = i >> 7, d = i & 127;
        sm.Q[r][d] = qn[(size_t)(qb + r) * (NH * NOPE) + h * NOPE + d];
    }
    for (int i = tid; i < BQ * ROPE; i += 256) {
        int r = i >> 6, d = i & 63;
        sm.Q[r][128 + d] = qr[(size_t)(qb + r) * (NH * ROPE) + h * ROPE + d];
    }

    const int ty = tid >> 4, tx = tid & 15;
    const int srow = tid >> 2, squad = tid & 3;

    float m = -1e30f, l = 0.f;
    float acc[4][8];
#pragma unroll
    for (int i = 0; i < 4; i++)
#pragma unroll
        for (int j = 0; j < 8; j++) acc[i][j] = 0.f;

    const int nkt = qt + 1;
    for (int kt = 0; kt < nkt; kt++) {
        const int kbT = b * S + kt * BKT;
        __syncthreads();

        for (int i = tid; i < BKT * NOPE; i += 256) {
            int r = i >> 7, d = i & 127;
            sm.K[r][d] = kn[(size_t)(kbT + r) * (NH * NOPE) + h * NOPE + d];
        }
        for (int i = tid; i < BKT * ROPE; i += 256) {
            int r = i >> 6, d = i & 63;
            sm.K[r][128 + d] = kr[(size_t)(kbT + r) * ROPE + d];
        }
        for (int i = tid; i < BKT * VD; i += 256) {
            int r = i >> 7, d = i & 127;
            sm.V[r][d] = v[(size_t)(kbT + r) * (NH * VD) + h * VD + d];
        }
        __syncthreads();

        float sacc[4][4];
#pragma unroll
        for (int i = 0; i < 4; i++)
#pragma unroll
            for (int j = 0; j < 4; j++) sacc[i][j] = 0.f;

#pragma unroll 4
        for (int d = 0; d < DQK; d += 4) {
            float4 qv[4], kv[4];
#pragma unroll
            for (int i = 0; i < 4; i++) qv[i] = *(const float4*)&sm.Q[ty * 4 + i][d];
#pragma unroll
            for (int j = 0; j < 4; j++) kv[j] = *(const float4*)&sm.K[tx * 4 + j][d];
#pragma unroll
            for (int i = 0; i < 4; i++)
#pragma unroll
                for (int j = 0; j < 4; j++)
                    sacc[i][j] += qv[i].x * kv[j].x + qv[i].y * kv[j].y
                                + qv[i].z * kv[j].z + qv[i].w * kv[j].w;
        }

        const bool diag = (kt == qt);
#pragma unroll
        for (int i = 0; i < 4; i++) {
            int qi = qt * BQ + ty * 4 + i;
#pragma unroll
            for (int j = 0; j < 4; j++) {
                int ki = kt * BKT + tx * 4 + j;
                float sv = sacc[i][j] * SM_SCALE;
                if (diag && ki > qi) sv = -1e9f;
                sm.P[ty * 4 + i][tx * 4 + j] = sv;
            }
        }
        __syncthreads();

        {
            float sv[16];
            float tmax = -1e30f;
#pragma unroll
            for (int jj = 0; jj < 16; jj++) {
                sv[jj] = sm.P[srow][squad * 16 + jj];
                tmax = fmaxf(tmax, sv[jj]);
            }
            tmax = fmaxf(tmax, __shfl_xor_sync(0xffffffffu, tmax, 1));
            tmax = fmaxf(tmax, __shfl_xor_sync(0xffffffffu, tmax, 2));
            float mnew = fmaxf(m, tmax);
            float al   = expf(m - mnew);
            float ps = 0.f;
#pragma unroll
            for (int jj = 0; jj < 16; jj++) {
                float p = expf(sv[jj] - mnew);
                sm.P[srow][squad * 16 + jj] = p;
                ps += p;
            }
            ps += __shfl_xor_sync(0xffffffffu, ps, 1);
            ps += __shfl_xor_sync(0xffffffffu, ps, 2);
            l = l * al + ps;
            m = mnew;
            if (squad == 0) sm.alpha[srow] = al;
        }
        __syncthreads();

        {
            float al[4];
#pragma unroll
            for (int i = 0; i < 4; i++) al[i] = sm.alpha[ty * 4 + i];
#pragma unroll
            for (int i = 0; i < 4; i++)
#pragma unroll
                for (int j = 0; j < 8; j++) acc[i][j] *= al[i];

#pragma unroll 2
            for (int kj = 0; kj < BKT; kj++) {
                float4 v0 = *(const float4*)&sm.V[kj][tx * 8];
                float4 v1 = *(const float4*)&sm.V[kj][tx * 8 + 4];
                float pv[4];
#pragma unroll
                for (int i = 0; i < 4; i++) pv[i] = sm.P[ty * 4 + i][kj];
#pragma unroll
                for (int i = 0; i < 4; i++) {
                    acc[i][0] += pv[i] * v0.x;
                    acc[i][1] += pv[i] * v0.y;
                    acc[i][2] += pv[i] * v0.z;
                    acc[i][3] += pv[i] * v0.w;
                    acc[i][4] += pv[i] * v1.x;
                    acc[i][5] += pv[i] * v1.y;
                    acc[i][6] += pv[i] * v1.z;
                    acc[i][7] += pv[i] * v1.w;
                }
            }
        }
    }

    if (squad == 0) sm.invl[srow] = 1.f / l;
    __syncthreads();

#pragma unroll
    for (int i = 0; i < 4; i++) {
        float sc = sm.invl[ty * 4 + i];
        int tokq = qb + ty * 4 + i;
#pragma unroll
        for (int j = 0; j < 8; j++)
            out[(size_t)tokq * (NH * VD) + h * VD + tx * 8 + j] = acc[i][j] * sc;
    }
}

// ---------------------------------------------------------------------------
// Launch
// ---------------------------------------------------------------------------
static void launch_gemm(const float* A, const float* B, float* C,
                        int M, int N, int K)
{
    dim3 grid((N + 127) / 128, (M + 127) / 128);
    tf32_gemm_kernel<<<grid, 256>>>(A, B, C, M, N, K);
}

extern "C" void kernel_launch(void* const* d_in, const int* in_sizes, int n_in,
                              void* d_out, int out_size)
{
    const float* x         = (const float*)d_in[0];
    const float* W_cq      = (const float*)d_in[1];
    const float* q_scale   = (const float*)d_in[2];
    const float* W_dq_nope = (const float*)d_in[3];
    const float* W_dq_rope = (const float*)d_in[4];
    const float* W_ckv     = (const float*)d_in[5];
    const float* kv_scale  = (const float*)d_in[6];
    const float* W_dk_nope = (const float*)d_in[7];
    const float* W_dv      = (const float*)d_in[8];
    const float* W_krope   = (const float*)d_in[9];
    const float* W_o       = (const float*)d_in[10];
    float* out = (float*)d_out;

    float *cq, *qn, *qr, *ckv, *kn, *vv, *kr, *att, *ctab, *stab;
    cudaGetSymbolAddress((void**)&cq,  g_cq);
    cudaGetSymbolAddress((void**)&qn,  g_qnope);
    cudaGetSymbolAddress((void**)&qr,  g_qrope);
    cudaGetSymbolAddress((void**)&ckv, g_ckv);
    cudaGetSymbolAddress((void**)&kn,  g_knope);
    cudaGetSymbolAddress((void**)&vv,  g_v);
    cudaGetSymbolAddress((void**)&kr,  g_krope);
    cudaGetSymbolAddress((void**)&att, g_attn);
    cudaGetSymbolAddress((void**)&ctab, g_ctab);
    cudaGetSymbolAddress((void**)&stab, g_stab);

    // RoPE tables
    rope_table_kernel<<<(S * 32 + 255) / 256, 256>>>(ctab, stab);

    // Q path
    launch_gemm(x, W_cq, cq, T, QR, H);
    rmsnorm_kernel<<<T, 256>>>(cq, q_scale, QR);
    launch_gemm(cq, W_dq_nope, qn, T, NH * NOPE, QR);
    launch_gemm(cq, W_dq_rope, qr, T, NH * ROPE, QR);
    rope_q_kernel<<<(T * NH * 32 + 255) / 256, 256>>>(qr, ctab, stab);

    // KV path
    launch_gemm(x, W_ckv, ckv, T, KVR, H);
    rmsnorm_kernel<<<T, 256>>>(ckv, kv_scale, KVR);
    launch_gemm(ckv, W_dk_nope, kn, T, NH * NOPE, KVR);
    launch_gemm(ckv, W_dv, vv, T, NH * VD, KVR);
    launch_gemm(x, W_krope, kr, T, ROPE, H);
    rope_k_kernel<<<(T * 32 + 255) / 256, 256>>>(kr, ctab, stab);

    // Attention
    cudaFuncSetAttribute((const void*)attn_kernel,
                         cudaFuncAttributeMaxDynamicSharedMemorySize,
                         (int)sizeof(AttnSmem));
    attn_kernel<<<dim3(S / BQ, NH, BB), 256, sizeof(AttnSmem)>>>(qn, qr, kn, kr, vv, att);

    // Output projection
    launch_gemm(att, W_o, out, T, H, NH * VD);
}

// round 3
// speedup vs baseline: 1.4717x; 1.0135x over previous
#include <cuda_runtime.h>
#include <math.h>
#include <stdint.h>

// ---------------------------------------------------------------------------
// Problem constants
// ---------------------------------------------------------------------------
constexpr int H    = 2048;
constexpr int NH   = 16;
constexpr int NOPE = 128;
constexpr int ROPE = 64;
constexpr int VD   = 128;
constexpr int QR   = 1024;
constexpr int KVR  = 512;
constexpr int BB   = 2;       // batch
constexpr int S    = 2048;    // seq len
constexpr int T    = BB * S;  // 4096 tokens
constexpr float EPS = 1e-6f;
constexpr float SM_SCALE = 0.07216878364870323f; // 1/sqrt(192)

// ---------------------------------------------------------------------------
// Device scratch (allocation-free rule: __device__ globals)
// ---------------------------------------------------------------------------
__device__ float g_cq   [T * QR];
__device__ float g_qnope[T * NH * NOPE];
__device__ float g_qrope[T * NH * ROPE];
__device__ float g_ckv  [T * KVR];
__device__ float g_knope[T * NH * NOPE];
__device__ float g_v    [T * NH * VD];
__device__ float g_krope[T * ROPE];
__device__ float g_attn [T * NH * VD];
__device__ float g_ctab [S * (ROPE / 2)];
__device__ float g_stab [S * (ROPE / 2)];

// ---------------------------------------------------------------------------
// tf32 helpers
// ---------------------------------------------------------------------------
__device__ __forceinline__ float to_tf32(float x) {
    uint32_t u;
    asm("cvt.rna.tf32.f32 %0, %1;" : "=r"(u) : "f"(x));
    return __uint_as_float(u);
}

__device__ __forceinline__ void mma_tf32(float& c0, float& c1, float& c2, float& c3,
                                         float a0, float a1, float a2, float a3,
                                         float b0, float b1)
{
    uint32_t ua0 = __float_as_uint(a0), ua1 = __float_as_uint(a1);
    uint32_t ua2 = __float_as_uint(a2), ua3 = __float_as_uint(a3);
    uint32_t ub0 = __float_as_uint(b0), ub1 = __float_as_uint(b1);
    asm volatile(
        "mma.sync.aligned.m16n8k8.row.col.f32.tf32.tf32.f32 "
        "{%0,%1,%2,%3}, {%4,%5,%6,%7}, {%8,%9}, {%0,%1,%2,%3};\n"
        : "+f"(c0), "+f"(c1), "+f"(c2), "+f"(c3)
        : "r"(ua0), "r"(ua1), "r"(ua2), "r"(ua3), "r"(ub0), "r"(ub1));
}

// Fragment-order smem stores (m16n8k8). A operand: element (m,k).
// lane=(m%8)*4+(k%4), slot=((m%16)/8)+2*((k%8)/4). Quad along k -> +4 floats.
// KSTEPS = number of 8-wide k-steps in the tile.
template<int KSTEPS>
__device__ __forceinline__ void st_afrag(float* F, int m, int k, float4 v) {
    float* dst = F + (((m >> 4) * KSTEPS + (k >> 3)) * 32 + (m & 7) * 4 + (k & 3)) * 4
                   + ((m >> 3) & 1) + (((k >> 2) & 1) << 1);
    dst[0]  = to_tf32(v.x);
    dst[4]  = to_tf32(v.y);
    dst[8]  = to_tf32(v.z);
    dst[12] = to_tf32(v.w);
}
// B operand, k varies along the float4 (attention K tile): element (n=r, k=d).
// lane=(n%8)*4+(k%4), slot=(k%8)/4. Quad along k -> +2 floats.
template<int KSTEPS>
__device__ __forceinline__ void st_bfrag_kvar(float* F, int r, int d, float4 v) {
    float* dst = F + (((r >> 3) * KSTEPS + (d >> 3)) * 32 + (r & 7) * 4 + (d & 3)) * 2
                   + ((d >> 2) & 1);
    dst[0] = to_tf32(v.x);
    dst[2] = to_tf32(v.y);
    dst[4] = to_tf32(v.z);
    dst[6] = to_tf32(v.w);
}
// B operand, n varies along the float4 (GEMM B tile): element (k, n..n+3).
// lane=(n%8)*4+(k%4) -> +4 lanes per elem -> +8 floats.
template<int KSTEPS>
__device__ __forceinline__ void st_bfrag_nvar(float* F, int k, int n, float4 v) {
    float* dst = F + (((n >> 3) * KSTEPS + (k >> 3)) * 32 + (n & 7) * 4 + (k & 3)) * 2
                   + ((k >> 2) & 1);
    dst[0]  = to_tf32(v.x);
    dst[8]  = to_tf32(v.y);
    dst[16] = to_tf32(v.z);
    dst[24] = to_tf32(v.w);
}

// ---------------------------------------------------------------------------
// tf32 tensor-core GEMM, fragment-preswizzled smem.
// C[M,N] = A[M,K] @ B[K,N] row-major fp32. 128x128 tile, BK=16, 256 thr.
// ---------------------------------------------------------------------------
__global__ void __launch_bounds__(256)
tf32_gemm_kernel(const float* __restrict__ A, const float* __restrict__ B,
                 float* __restrict__ C, int M, int N, int K)
{
    __shared__ float Af[2][8 * 2 * 32 * 4];   // [buf][mtile(8)][kstep(2)][lane][slot4]
    __shared__ float Bf[2][16 * 2 * 32 * 2];  // [buf][ntile(16)][kstep(2)][lane][slot2]

    const int tid  = threadIdx.x;
    const int lane = tid & 31;
    const int warp = tid >> 5;
    const int qid  = lane >> 2;
    const int rid  = lane & 3;
    const int wrm  = (warp >> 2) * 4;   // mtile base (rows (warp>>2)*64)
    const int wcn  = (warp & 3) * 4;    // ntile base (cols (warp&3)*32)
    const int wr   = wrm * 16;
    const int wc   = wcn * 8;

    const int rowBase = blockIdx.y * 128;
    const int colBase = blockIdx.x * 128;

    const int ar0 = tid >> 2;
    const int ar1 = ar0 + 64;
    const int ac  = (tid & 3) * 4;
    const int bk0 = tid >> 5;
    const int bk1 = bk0 + 8;
    const int bn  = (tid & 31) * 4;
    const int gn  = colBase + bn;
    const bool bok = (gn < N);

    float acc[4][4][4];
#pragma unroll
    for (int i = 0; i < 4; i++)
#pragma unroll
        for (int j = 0; j < 4; j++)
#pragma unroll
            for (int c = 0; c < 4; c++) acc[i][j][c] = 0.f;

    const int nt = K / 16;
    float4 ra0, ra1, rb0, rb1;

    // prologue
    ra0 = *(const float4*)&A[(size_t)(rowBase + ar0) * K + ac];
    ra1 = *(const float4*)&A[(size_t)(rowBase + ar1) * K + ac];
    rb0 = bok ? *(const float4*)&B[(size_t)bk0 * N + gn] : make_float4(0,0,0,0);
    rb1 = bok ? *(const float4*)&B[(size_t)bk1 * N + gn] : make_float4(0,0,0,0);
    st_afrag<2>(Af[0], ar0, ac, ra0);
    st_afrag<2>(Af[0], ar1, ac, ra1);
    st_bfrag_nvar<2>(Bf[0], bk0, bn, rb0);
    st_bfrag_nvar<2>(Bf[0], bk1, bn, rb1);
    __syncthreads();

    for (int t = 0; t < nt; t++) {
        const int buf = t & 1;

        if (t + 1 < nt) {
            const int k0 = (t + 1) * 16;
            ra0 = *(const float4*)&A[(size_t)(rowBase + ar0) * K + k0 + ac];
            ra1 = *(const float4*)&A[(size_t)(rowBase + ar1) * K + k0 + ac];
            rb0 = bok ? *(const float4*)&B[(size_t)(k0 + bk0) * N + gn] : make_float4(0,0,0,0);
            rb1 = bok ? *(const float4*)&B[(size_t)(k0 + bk1) * N + gn] : make_float4(0,0,0,0);
        }

#pragma unroll
        for (int ks = 0; ks < 2; ks++) {
            float4 a[4];
            float2 b[4];
#pragma unroll
            for (int i = 0; i < 4; i++)
                a[i] = *(const float4*)&Af[buf][(((wrm + i) * 2 + ks) * 32 + lane) * 4];
#pragma unroll
            for (int j = 0; j < 4; j++)
                b[j] = *(const float2*)&Bf[buf][(((wcn + j) * 2 + ks) * 32 + lane) * 2];
#pragma unroll
            for (int i = 0; i < 4; i++)
#pragma unroll
                for (int j = 0; j < 4; j++)
                    mma_tf32(acc[i][j][0], acc[i][j][1], acc[i][j][2], acc[i][j][3],
                             a[i].x, a[i].y, a[i].z, a[i].w, b[j].x, b[j].y);
        }

        if (t + 1 < nt) {
            const int nb = (t + 1) & 1;
            st_afrag<2>(Af[nb], ar0, ac, ra0);
            st_afrag<2>(Af[nb], ar1, ac, ra1);
            st_bfrag_nvar<2>(Bf[nb], bk0, bn, rb0);
            st_bfrag_nvar<2>(Bf[nb], bk1, bn, rb1);
        }
        __syncthreads();
    }

#pragma unroll
    for (int i = 0; i < 4; i++) {
        const int r0 = rowBase + wr + i * 16 + qid;
#pragma unroll
        for (int j = 0; j < 4; j++) {
            const int col = colBase + wc + j * 8 + rid * 2;
            if (col < N) {
                *(float2*)&C[(size_t)r0 * N + col]       = make_float2(acc[i][j][0], acc[i][j][1]);
                *(float2*)&C[(size_t)(r0 + 8) * N + col] = make_float2(acc[i][j][2], acc[i][j][3]);
            }
        }
    }
}

// ---------------------------------------------------------------------------
// RMSNorm (in place)
// ---------------------------------------------------------------------------
__global__ void rmsnorm_kernel(float* __restrict__ x,
                               const float* __restrict__ scale, int D)
{
    __shared__ float red[32];
    float* p = x + (size_t)blockIdx.x * D;

    float ss = 0.f;
    for (int d = threadIdx.x; d < D; d += blockDim.x) {
        float v = p[d];
        ss += v * v;
    }
#pragma unroll
    for (int o = 16; o; o >>= 1) ss += __shfl_xor_sync(0xffffffffu, ss, o);
    if ((threadIdx.x & 31) == 0) red[threadIdx.x >> 5] = ss;
    __syncthreads();
    if (threadIdx.x < 32) {
        float v = (threadIdx.x < (blockDim.x >> 5)) ? red[threadIdx.x] : 0.f;
#pragma unroll
        for (int o = 16; o; o >>= 1) v += __shfl_xor_sync(0xffffffffu, v, o);
        if (threadIdx.x == 0) red[0] = v;
    }
    __syncthreads();
    float inv = rsqrtf(red[0] / (float)D + EPS);
    for (int d = threadIdx.x; d < D; d += blockDim.x)
        p[d] = p[d] * inv * scale[d];
}

// ---------------------------------------------------------------------------
// RoPE tables / application
// ---------------------------------------------------------------------------
__global__ void rope_table_kernel(float* __restrict__ ctab, float* __restrict__ stab)
{
    int idx = blockIdx.x * blockDim.x + threadIdx.x;
    if (idx >= S * (ROPE / 2)) return;
    int i = idx % (ROPE / 2);
    int s = idx / (ROPE / 2);
    float freq = (float)pow(10000.0, -((double)(2 * i)) / (double)ROPE);
    float ang  = (float)s * freq;
    double a   = (double)ang;
    ctab[idx] = (float)cos(a);
    stab[idx] = (float)sin(a);
}

__global__ void rope_q_kernel(float* __restrict__ q,
                              const float* __restrict__ ctab,
                              const float* __restrict__ stab)
{
    int idx = blockIdx.x * blockDim.x + threadIdx.x;
    if (idx >= T * NH * (ROPE / 2)) return;
    int i   = idx & 31;
    int rem = idx >> 5;
    int h   = rem & (NH - 1);
    int tok = rem >> 4;
    int s   = tok & (S - 1);
    float c  = ctab[s * 32 + i];
    float sn = stab[s * 32 + i];
    float* p = q + (size_t)tok * (NH * ROPE) + h * ROPE + 2 * i;
    float x1 = p[0], x2 = p[1];
    p[0] = x1 * c - x2 * sn;
    p[1] = x1 * sn + x2 * c;
}

__global__ void rope_k_kernel(float* __restrict__ k,
                              const float* __restrict__ ctab,
                              const float* __restrict__ stab)
{
    int idx = blockIdx.x * blockDim.x + threadIdx.x;
    if (idx >= T * (ROPE / 2)) return;
    int i   = idx & 31;
    int tok = idx >> 5;
    int s   = tok & (S - 1);
    float c  = ctab[s * 32 + i];
    float sn = stab[s * 32 + i];
    float* p = k + (size_t)tok * ROPE + 2 * i;
    float x1 = p[0], x2 = p[1];
    p[0] = (x1 * c - x2 * sn) * 0.0625f;   // /NH folded in
    p[1] = (x1 * sn + x2 * c) * 0.0625f;
}

// ---------------------------------------------------------------------------
// Flash attention: QK^T on tf32 mma (fragment-preswizzled Q/K), softmax with
// __expf, PV in fp32 FFMA. Causal, online softmax, exact -1e9 diagonal mask.
// ---------------------------------------------------------------------------
constexpr int BQ  = 64;
constexpr int BKT = 64;

struct AttnSmem {
    float Qf[4 * 24 * 32 * 4];   // A-frag layout: [mtile][kstep][lane][slot]
    float Kf[8 * 24 * 32 * 2];   // B-frag layout: [ntile][kstep][lane][slot]
    float V[BKT][132];
    float P[BQ][68];
    float alpha[BQ];
    float invl[BQ];
};

__global__ void __launch_bounds__(256)
attn_kernel(const float* __restrict__ qn, const float* __restrict__ qr,
            const float* __restrict__ kn, const float* __restrict__ kr,
            const float* __restrict__ v,  float* __restrict__ out)
{
    extern __shared__ char smraw[];
    AttnSmem& sm = *reinterpret_cast<AttnSmem*>(smraw);

    const int qt = blockIdx.x;
    const int h  = blockIdx.y;
    const int b  = blockIdx.z;
    const int tid = threadIdx.x;
    const int lane = tid & 31;
    const int warp = tid >> 5;
    const int qb = b * S + qt * BQ;

    // warp mapping for QK mma: 4x2 warps -> rows (warp&3)*16, cols (warp>>2)*32
    const int mtile = warp & 3;
    const int ntb   = (warp >> 2) * 4;

    // ---- load Q tile into fragment layout ----
    for (int idx = tid; idx < BQ * 32; idx += 256) {       // nope: 64 x 32 float4
        int r = idx >> 5, dq = (idx & 31) * 4;
        float4 vq = *(const float4*)&qn[(size_t)(qb + r) * (NH * NOPE) + h * NOPE + dq];
        st_afrag<24>(sm.Qf, r, dq, vq);
    }
    for (int idx = tid; idx < BQ * 16; idx += 256) {       // rope: 64 x 16 float4
        int r = idx >> 4, dq = (idx & 15) * 4;
        float4 vq = *(const float4*)&qr[(size_t)(qb + r) * (NH * ROPE) + h * ROPE + dq];
        st_afrag<24>(sm.Qf, r, 128 + dq, vq);
    }

    const int ty = tid >> 4, tx = tid & 15;       // PV mapping (16x16)
    const int srow = tid >> 2, squad = tid & 3;   // softmax mapping (64 x 4)

    float m = -1e30f, l = 0.f;
    float acc[4][8];
#pragma unroll
    for (int i = 0; i < 4; i++)
#pragma unroll
        for (int j = 0; j < 8; j++) acc[i][j] = 0.f;

    const int nkt = qt + 1;                       // causal tile skip
    for (int kt = 0; kt < nkt; kt++) {
        const int kbT = b * S + kt * BKT;
        __syncthreads();   // previous iteration done with K/V/P

        // ---- load K tile (frag layout) + V tile (raw) ----
        for (int idx = tid; idx < BKT * 32; idx += 256) {
            int r = idx >> 5, dq = (idx & 31) * 4;
            float4 vk = *(const float4*)&kn[(size_t)(kbT + r) * (NH * NOPE) + h * NOPE + dq];
            st_bfrag_kvar<24>(sm.Kf, r, dq, vk);
        }
        for (int idx = tid; idx < BKT * 16; idx += 256) {
            int r = idx >> 4, dq = (idx & 15) * 4;
            float4 vk = *(const float4*)&kr[(size_t)(kbT + r) * ROPE + dq];
            st_bfrag_kvar<24>(sm.Kf, r, 128 + dq, vk);
        }
        for (int idx = tid; idx < BKT * 32; idx += 256) {
            int r = idx >> 5, dq = (idx & 31) * 4;
            *(float4*)&sm.V[r][dq] = *(const float4*)&v[(size_t)(kbT + r) * (NH * VD) + h * VD + dq];
        }
        __syncthreads();

        // ---- scores via tf32 mma: warp computes 16x32 ----
        {
            float c[4][4];
#pragma unroll
            for (int j = 0; j < 4; j++)
#pragma unroll
                for (int cc = 0; cc < 4; cc++) c[j][cc] = 0.f;

#pragma unroll
            for (int ks = 0; ks < 24; ks++) {
                float4 a = *(const float4*)&sm.Qf[((mtile * 24 + ks) * 32 + lane) * 4];
#pragma unroll
                for (int j = 0; j < 4; j++) {
                    float2 bb = *(const float2*)&sm.Kf[(((ntb + j) * 24 + ks) * 32 + lane) * 2];
                    mma_tf32(c[j][0], c[j][1], c[j][2], c[j][3],
                             a.x, a.y, a.z, a.w, bb.x, bb.y);
                }
            }

            const bool diag = (kt == qt);
            const int r0 = mtile * 16 + (lane >> 2);
#pragma unroll
            for (int j = 0; j < 4; j++) {
                int col = (ntb + j) * 8 + (lane & 3) * 2;
                int ki0 = kt * BKT + col;
                float s0 = c[j][0] * SM_SCALE, s1 = c[j][1] * SM_SCALE;
                float s2 = c[j][2] * SM_SCALE, s3 = c[j][3] * SM_SCALE;
                if (diag) {
                    int qi0 = qt * BQ + r0;
                    int qi1 = qi0 + 8;
                    if (ki0     > qi0) s0 = -1e9f;
                    if (ki0 + 1 > qi0) s1 = -1e9f;
                    if (ki0     > qi1) s2 = -1e9f;
                    if (ki0 + 1 > qi1) s3 = -1e9f;
                }
                *(float2*)&sm.P[r0][col]     = make_float2(s0, s1);
                *(float2*)&sm.P[r0 + 8][col] = make_float2(s2, s3);
            }
        }
        __syncthreads();

        // ---- online softmax ----
        {
            float sv[16];
            float tmax = -1e30f;
#pragma unroll
            for (int jj = 0; jj < 16; jj++) {
                sv[jj] = sm.P[srow][squad * 16 + jj];
                tmax = fmaxf(tmax, sv[jj]);
            }
            tmax = fmaxf(tmax, __shfl_xor_sync(0xffffffffu, tmax, 1));
            tmax = fmaxf(tmax, __shfl_xor_sync(0xffffffffu, tmax, 2));
            float mnew = fmaxf(m, tmax);
            float al   = __expf(m - mnew);
            float ps = 0.f;
#pragma unroll
            for (int jj = 0; jj < 16; jj++) {
                float p = __expf(sv[jj] - mnew);
                sm.P[srow][squad * 16 + jj] = p;
                ps += p;
            }
            ps += __shfl_xor_sync(0xffffffffu, ps, 1);
            ps += __shfl_xor_sync(0xffffffffu, ps, 2);
            l = l * al + ps;
            m = mnew;
            if (squad == 0) sm.alpha[srow] = al;
        }
        __syncthreads();

        // ---- O = O*alpha + P @ V (fp32) ----
        {
            float al[4];
#pragma unroll
            for (int i = 0; i < 4; i++) al[i] = sm.alpha[ty * 4 + i];
#pragma unroll
            for (int i = 0; i < 4; i++)
#pragma unroll
                for (int j = 0; j < 8; j++) acc[i][j] *= al[i];

#pragma unroll 2
            for (int kj = 0; kj < BKT; kj++) {
                float4 v0 = *(const float4*)&sm.V[kj][tx * 8];
                float4 v1 = *(const float4*)&sm.V[kj][tx * 8 + 4];
                float pv[4];
#pragma unroll
                for (int i = 0; i < 4; i++) pv[i] = sm.P[ty * 4 + i][kj];
#pragma unroll
                for (int i = 0; i < 4; i++) {
                    acc[i][0] += pv[i] * v0.x;
                    acc[i][1] += pv[i] * v0.y;
                    acc[i][2] += pv[i] * v0.z;
                    acc[i][3] += pv[i] * v0.w;
                    acc[i][4] += pv[i] * v1.x;
                    acc[i][5] += pv[i] * v1.y;
                    acc[i][6] += pv[i] * v1.z;
                    acc[i][7] += pv[i] * v1.w;
                }
            }
        }
    }

    if (squad == 0) sm.invl[srow] = 1.f / l;
    __syncthreads();

#pragma unroll
    for (int i = 0; i < 4; i++) {
        float sc = sm.invl[ty * 4 + i];
        int tokq = qb + ty * 4 + i;
#pragma unroll
        for (int j = 0; j < 8; j++)
            out[(size_t)tokq * (NH * VD) + h * VD + tx * 8 + j] = acc[i][j] * sc;
    }
}

// ---------------------------------------------------------------------------
// Launch
// ---------------------------------------------------------------------------
static void launch_gemm(const float* A, const float* B, float* C,
                        int M, int N, int K)
{
    dim3 grid((N + 127) / 128, (M + 127) / 128);
    tf32_gemm_kernel<<<grid, 256>>>(A, B, C, M, N, K);
}

extern "C" void kernel_launch(void* const* d_in, const int* in_sizes, int n_in,
                              void* d_out, int out_size)
{
    const float* x         = (const float*)d_in[0];
    const float* W_cq      = (const float*)d_in[1];
    const float* q_scale   = (const float*)d_in[2];
    const float* W_dq_nope = (const float*)d_in[3];
    const float* W_dq_rope = (const float*)d_in[4];
    const float* W_ckv     = (const float*)d_in[5];
    const float* kv_scale  = (const float*)d_in[6];
    const float* W_dk_nope = (const float*)d_in[7];
    const float* W_dv      = (const float*)d_in[8];
    const float* W_krope   = (const float*)d_in[9];
    const float* W_o       = (const float*)d_in[10];
    float* out = (float*)d_out;

    float *cq, *qn, *qr, *ckv, *kn, *vv, *kr, *att, *ctab, *stab;
    cudaGetSymbolAddress((void**)&cq,  g_cq);
    cudaGetSymbolAddress((void**)&qn,  g_qnope);
    cudaGetSymbolAddress((void**)&qr,  g_qrope);
    cudaGetSymbolAddress((void**)&ckv, g_ckv);
    cudaGetSymbolAddress((void**)&kn,  g_knope);
    cudaGetSymbolAddress((void**)&vv,  g_v);
    cudaGetSymbolAddress((void**)&kr,  g_krope);
    cudaGetSymbolAddress((void**)&att, g_attn);
    cudaGetSymbolAddress((void**)&ctab, g_ctab);
    cudaGetSymbolAddress((void**)&stab, g_stab);

    // RoPE tables
    rope_table_kernel<<<(S * 32 + 255) / 256, 256>>>(ctab, stab);

    // Q path
    launch_gemm(x, W_cq, cq, T, QR, H);
    rmsnorm_kernel<<<T, 256>>>(cq, q_scale, QR);
    launch_gemm(cq, W_dq_nope, qn, T, NH * NOPE, QR);
    launch_gemm(cq, W_dq_rope, qr, T, NH * ROPE, QR);
    rope_q_kernel<<<(T * NH * 32 + 255) / 256, 256>>>(qr, ctab, stab);

    // KV path
    launch_gemm(x, W_ckv, ckv, T, KVR, H);
    rmsnorm_kernel<<<T, 256>>>(ckv, kv_scale, KVR);
    launch_gemm(ckv, W_dk_nope, kn, T, NH * NOPE, KVR);
    launch_gemm(ckv, W_dv, vv, T, NH * VD, KVR);
    launch_gemm(x, W_krope, kr, T, ROPE, H);
    rope_k_kernel<<<(T * 32 + 255) / 256, 256>>>(kr, ctab, stab);

    // Attention
    cudaFuncSetAttribute((const void*)attn_kernel,
                         cudaFuncAttributeMaxDynamicSharedMemorySize,
                         (int)sizeof(AttnSmem));
    attn_kernel<<<dim3(S / BQ, NH, BB), 256, sizeof(AttnSmem)>>>(qn, qr, kn, kr, vv, att);

    // Output projection
    launch_gemm(att, W_o, out, T, H, NH * VD);
}

// round 4
// speedup vs baseline: 2.4890x; 1.6912x over previous
#include <cuda_runtime.h>
#include <math.h>
#include <stdint.h>

// ---------------------------------------------------------------------------
// Problem constants
// ---------------------------------------------------------------------------
constexpr int H    = 2048;
constexpr int NH   = 16;
constexpr int NOPE = 128;
constexpr int ROPE = 64;
constexpr int VD   = 128;
constexpr int QR   = 1024;
constexpr int KVR  = 512;
constexpr int BB   = 2;       // batch
constexpr int S    = 2048;    // seq len
constexpr int T    = BB * S;  // 4096 tokens
constexpr float EPS = 1e-6f;
constexpr float SM_SCALE = 0.07216878364870323f; // 1/sqrt(192)

// ---------------------------------------------------------------------------
// Device scratch (allocation-free rule: __device__ globals)
// ---------------------------------------------------------------------------
__device__ float g_cq   [T * QR];
__device__ float g_qnope[T * NH * NOPE];
__device__ float g_qrope[T * NH * ROPE];
__device__ float g_ckv  [T * KVR];
__device__ float g_knope[T * NH * NOPE];
__device__ float g_v    [T * NH * VD];
__device__ float g_krope[T * ROPE];
__device__ float g_attn [T * NH * VD];
__device__ float g_ctab [S * (ROPE / 2)];
__device__ float g_stab [S * (ROPE / 2)];

// ---------------------------------------------------------------------------
// tf32 helpers
// ---------------------------------------------------------------------------
__device__ __forceinline__ float to_tf32(float x) {
    uint32_t u;
    asm("cvt.rna.tf32.f32 %0, %1;" : "=r"(u) : "f"(x));
    return __uint_as_float(u);
}
__device__ __forceinline__ float4 to_tf32x4(float4 v) {
    return make_float4(to_tf32(v.x), to_tf32(v.y), to_tf32(v.z), to_tf32(v.w));
}

__device__ __forceinline__ void mma_tf32(float& c0, float& c1, float& c2, float& c3,
                                         float a0, float a1, float a2, float a3,
                                         float b0, float b1)
{
    uint32_t ua0 = __float_as_uint(a0), ua1 = __float_as_uint(a1);
    uint32_t ua2 = __float_as_uint(a2), ua3 = __float_as_uint(a3);
    uint32_t ub0 = __float_as_uint(b0), ub1 = __float_as_uint(b1);
    asm volatile(
        "mma.sync.aligned.m16n8k8.row.col.f32.tf32.tf32.f32 "
        "{%0,%1,%2,%3}, {%4,%5,%6,%7}, {%8,%9}, {%0,%1,%2,%3};\n"
        : "+f"(c0), "+f"(c1), "+f"(c2), "+f"(c3)
        : "r"(ua0), "r"(ua1), "r"(ua2), "r"(ua3), "r"(ub0), "r"(ub1));
}

// Fragment-order smem stores used by the ATTENTION kernel only (amortized
// over 8 warps x 24 k-steps there; too store-heavy for the GEMM).
template<int KSTEPS>
__device__ __forceinline__ void st_afrag(float* F, int m, int k, float4 v) {
    float* dst = F + (((m >> 4) * KSTEPS + (k >> 3)) * 32 + (m & 7) * 4 + (k & 3)) * 4
                   + ((m >> 3) & 1) + (((k >> 2) & 1) << 1);
    dst[0]  = to_tf32(v.x);
    dst[4]  = to_tf32(v.y);
    dst[8]  = to_tf32(v.z);
    dst[12] = to_tf32(v.w);
}
template<int KSTEPS>
__device__ __forceinline__ void st_bfrag_kvar(float* F, int r, int d, float4 v) {
    float* dst = F + (((r >> 3) * KSTEPS + (d >> 3)) * 32 + (r & 7) * 4 + (d & 3)) * 2
                   + ((d >> 2) & 1);
    dst[0] = to_tf32(v.x);
    dst[2] = to_tf32(v.y);
    dst[4] = to_tf32(v.z);
    dst[6] = to_tf32(v.w);
}

// ---------------------------------------------------------------------------
// tf32 tensor-core GEMM (round-2 proven version): C[M,N] = A[M,K] @ B[K,N].
// 128x128 block tile, BK=16, 256 threads, warp tile 64x32, double-buffered
// smem with padded strides (conflict-free fragment reads).
// ---------------------------------------------------------------------------
constexpr int AS_STRIDE = 20;
constexpr int BS_STRIDE = 136;

__global__ void __launch_bounds__(256)
tf32_gemm_kernel(const float* __restrict__ A, const float* __restrict__ B,
                 float* __restrict__ C, int M, int N, int K)
{
    __shared__ float As[2][128][AS_STRIDE];
    __shared__ float Bs[2][16][BS_STRIDE];

    const int tid  = threadIdx.x;
    const int lane = tid & 31;
    const int warp = tid >> 5;
    const int qid  = lane >> 2;
    const int rid  = lane & 3;
    const int wr   = (warp >> 2) * 64;
    const int wc   = (warp & 3) * 32;

    const int rowBase = blockIdx.y * 128;
    const int colBase = blockIdx.x * 128;

    const int ar0 = tid >> 2;
    const int ar1 = ar0 + 64;
    const int ac  = (tid & 3) * 4;
    const int bk0 = tid >> 5;
    const int bk1 = bk0 + 8;
    const int bn  = (tid & 31) * 4;
    const int gn  = colBase + bn;
    const bool bok = (gn < N);

    float acc[4][4][4];
#pragma unroll
    for (int i = 0; i < 4; i++)
#pragma unroll
        for (int j = 0; j < 4; j++)
#pragma unroll
            for (int c = 0; c < 4; c++) acc[i][j][c] = 0.f;

    const int nt = K / 16;
    float4 ra0, ra1, rb0, rb1;

    // prologue: tile 0
    ra0 = *(const float4*)&A[(size_t)(rowBase + ar0) * K + ac];
    ra1 = *(const float4*)&A[(size_t)(rowBase + ar1) * K + ac];
    rb0 = bok ? *(const float4*)&B[(size_t)bk0 * N + gn] : make_float4(0,0,0,0);
    rb1 = bok ? *(const float4*)&B[(size_t)bk1 * N + gn] : make_float4(0,0,0,0);
    *(float4*)&As[0][ar0][ac] = to_tf32x4(ra0);
    *(float4*)&As[0][ar1][ac] = to_tf32x4(ra1);
    *(float4*)&Bs[0][bk0][bn] = to_tf32x4(rb0);
    *(float4*)&Bs[0][bk1][bn] = to_tf32x4(rb1);
    __syncthreads();

    for (int t = 0; t < nt; t++) {
        const int buf = t & 1;

        if (t + 1 < nt) {
            const int k0 = (t + 1) * 16;
            ra0 = *(const float4*)&A[(size_t)(rowBase + ar0) * K + k0 + ac];
            ra1 = *(const float4*)&A[(size_t)(rowBase + ar1) * K + k0 + ac];
            rb0 = bok ? *(const float4*)&B[(size_t)(k0 + bk0) * N + gn] : make_float4(0,0,0,0);
            rb1 = bok ? *(const float4*)&B[(size_t)(k0 + bk1) * N + gn] : make_float4(0,0,0,0);
        }

#pragma unroll
        for (int ks = 0; ks < 16; ks += 8) {
            float a[4][4], b[4][2];
#pragma unroll
            for (int i = 0; i < 4; i++) {
                const float* p0 = &As[buf][wr + i * 16 + qid][ks + rid];
                const float* p1 = &As[buf][wr + i * 16 + qid + 8][ks + rid];
                a[i][0] = p0[0];
                a[i][1] = p1[0];
                a[i][2] = p0[4];
                a[i][3] = p1[4];
            }
#pragma unroll
            for (int j = 0; j < 4; j++) {
                b[j][0] = Bs[buf][ks + rid][wc + j * 8 + qid];
                b[j][1] = Bs[buf][ks + rid + 4][wc + j * 8 + qid];
            }
#pragma unroll
            for (int i = 0; i < 4; i++)
#pragma unroll
                for (int j = 0; j < 4; j++)
                    mma_tf32(acc[i][j][0], acc[i][j][1], acc[i][j][2], acc[i][j][3],
                             a[i][0], a[i][1], a[i][2], a[i][3],
                             b[j][0], b[j][1]);
        }

        if (t + 1 < nt) {
            const int nb = (t + 1) & 1;
            *(float4*)&As[nb][ar0][ac] = to_tf32x4(ra0);
            *(float4*)&As[nb][ar1][ac] = to_tf32x4(ra1);
            *(float4*)&Bs[nb][bk0][bn] = to_tf32x4(rb0);
            *(float4*)&Bs[nb][bk1][bn] = to_tf32x4(rb1);
        }
        __syncthreads();
    }

#pragma unroll
    for (int i = 0; i < 4; i++) {
        const int r0 = rowBase + wr + i * 16 + qid;
#pragma unroll
        for (int j = 0; j < 4; j++) {
            const int col = colBase + wc + j * 8 + rid * 2;
            if (col < N) {
                *(float2*)&C[(size_t)r0 * N + col]       = make_float2(acc[i][j][0], acc[i][j][1]);
                *(float2*)&C[(size_t)(r0 + 8) * N + col] = make_float2(acc[i][j][2], acc[i][j][3]);
            }
        }
    }
}

// ---------------------------------------------------------------------------
// RMSNorm (in place)
// ---------------------------------------------------------------------------
__global__ void rmsnorm_kernel(float* __restrict__ x,
                               const float* __restrict__ scale, int D)
{
    __shared__ float red[32];
    float* p = x + (size_t)blockIdx.x * D;

    float ss = 0.f;
    for (int d = threadIdx.x; d < D; d += blockDim.x) {
        float v = p[d];
        ss += v * v;
    }
#pragma unroll
    for (int o = 16; o; o >>= 1) ss += __shfl_xor_sync(0xffffffffu, ss, o);
    if ((threadIdx.x & 31) == 0) red[threadIdx.x >> 5] = ss;
    __syncthreads();
    if (threadIdx.x < 32) {
        float v = (threadIdx.x < (blockDim.x >> 5)) ? red[threadIdx.x] : 0.f;
#pragma unroll
        for (int o = 16; o; o >>= 1) v += __shfl_xor_sync(0xffffffffu, v, o);
        if (threadIdx.x == 0) red[0] = v;
    }
    __syncthreads();
    float inv = rsqrtf(red[0] / (float)D + EPS);
    for (int d = threadIdx.x; d < D; d += blockDim.x)
        p[d] = p[d] * inv * scale[d];
}

// ---------------------------------------------------------------------------
// RoPE tables / application
// ---------------------------------------------------------------------------
__global__ void rope_table_kernel(float* __restrict__ ctab, float* __restrict__ stab)
{
    int idx = blockIdx.x * blockDim.x + threadIdx.x;
    if (idx >= S * (ROPE / 2)) return;
    int i = idx % (ROPE / 2);
    int s = idx / (ROPE / 2);
    float freq = (float)pow(10000.0, -((double)(2 * i)) / (double)ROPE);
    float ang  = (float)s * freq;
    double a   = (double)ang;
    ctab[idx] = (float)cos(a);
    stab[idx] = (float)sin(a);
}

__global__ void rope_q_kernel(float* __restrict__ q,
                              const float* __restrict__ ctab,
                              const float* __restrict__ stab)
{
    int idx = blockIdx.x * blockDim.x + threadIdx.x;
    if (idx >= T * NH * (ROPE / 2)) return;
    int i   = idx & 31;
    int rem = idx >> 5;
    int h   = rem & (NH - 1);
    int tok = rem >> 4;
    int s   = tok & (S - 1);
    float c  = ctab[s * 32 + i];
    float sn = stab[s * 32 + i];
    float* p = q + (size_t)tok * (NH * ROPE) + h * ROPE + 2 * i;
    float x1 = p[0], x2 = p[1];
    p[0] = x1 * c - x2 * sn;
    p[1] = x1 * sn + x2 * c;
}

__global__ void rope_k_kernel(float* __restrict__ k,
                              const float* __restrict__ ctab,
                              const float* __restrict__ stab)
{
    int idx = blockIdx.x * blockDim.x + threadIdx.x;
    if (idx >= T * (ROPE / 2)) return;
    int i   = idx & 31;
    int tok = idx >> 5;
    int s   = tok & (S - 1);
    float c  = ctab[s * 32 + i];
    float sn = stab[s * 32 + i];
    float* p = k + (size_t)tok * ROPE + 2 * i;
    float x1 = p[0], x2 = p[1];
    p[0] = (x1 * c - x2 * sn) * 0.0625f;   // /NH folded in
    p[1] = (x1 * sn + x2 * c) * 0.0625f;
}

// ---------------------------------------------------------------------------
// Flash attention: QK^T on tf32 mma (fragment-preswizzled Q/K), softmax with
// __expf, PV in fp32 FFMA. Causal, online softmax, exact -1e9 diagonal mask.
// ---------------------------------------------------------------------------
constexpr int BQ  = 64;
constexpr int BKT = 64;

struct AttnSmem {
    float Qf[4 * 24 * 32 * 4];   // A-frag layout: [mtile][kstep][lane][slot]
    float Kf[8 * 24 * 32 * 2];   // B-frag layout: [ntile][kstep][lane][slot]
    float V[BKT][132];
    float P[BQ][68];
    float alpha[BQ];
    float invl[BQ];
};

__global__ void __launch_bounds__(256)
attn_kernel(const float* __restrict__ qn, const float* __restrict__ qr,
            const float* __restrict__ kn, const float* __restrict__ kr,
            const float* __restrict__ v,  float* __restrict__ out)
{
    extern __shared__ char smraw[];
    AttnSmem& sm = *reinterpret_cast<AttnSmem*>(smraw);

    const int qt = blockIdx.x;
    const int h  = blockIdx.y;
    const int b  = blockIdx.z;
    const int tid = threadIdx.x;
    const int lane = tid & 31;
    const int warp = tid >> 5;
    const int qb = b * S + qt * BQ;

    const int mtile = warp & 3;
    const int ntb   = (warp >> 2) * 4;

    // ---- load Q tile into fragment layout ----
    for (int idx = tid; idx < BQ * 32; idx += 256) {
        int r = idx >> 5, dq = (idx & 31) * 4;
        float4 vq = *(const float4*)&qn[(size_t)(qb + r) * (NH * NOPE) + h * NOPE + dq];
        st_afrag<24>(sm.Qf, r, dq, vq);
    }
    for (int idx = tid; idx < BQ * 16; idx += 256) {
        int r = idx >> 4, dq = (idx & 15) * 4;
        float4 vq = *(const float4*)&qr[(size_t)(qb + r) * (NH * ROPE) + h * ROPE + dq];
        st_afrag<24>(sm.Qf, r, 128 + dq, vq);
    }

    const int ty = tid >> 4, tx = tid & 15;
    const int srow = tid >> 2, squad = tid & 3;

    float m = -1e30f, l = 0.f;
    float acc[4][8];
#pragma unroll
    for (int i = 0; i < 4; i++)
#pragma unroll
        for (int j = 0; j < 8; j++) acc[i][j] = 0.f;

    const int nkt = qt + 1;
    for (int kt = 0; kt < nkt; kt++) {
        const int kbT = b * S + kt * BKT;
        __syncthreads();

        for (int idx = tid; idx < BKT * 32; idx += 256) {
            int r = idx >> 5, dq = (idx & 31) * 4;
            float4 vk = *(const float4*)&kn[(size_t)(kbT + r) * (NH * NOPE) + h * NOPE + dq];
            st_bfrag_kvar<24>(sm.Kf, r, dq, vk);
        }
        for (int idx = tid; idx < BKT * 16; idx += 256) {
            int r = idx >> 4, dq = (idx & 15) * 4;
            float4 vk = *(const float4*)&kr[(size_t)(kbT + r) * ROPE + dq];
            st_bfrag_kvar<24>(sm.Kf, r, 128 + dq, vk);
        }
        for (int idx = tid; idx < BKT * 32; idx += 256) {
            int r = idx >> 5, dq = (idx & 31) * 4;
            *(float4*)&sm.V[r][dq] = *(const float4*)&v[(size_t)(kbT + r) * (NH * VD) + h * VD + dq];
        }
        __syncthreads();

        // ---- scores via tf32 mma: warp computes 16x32 ----
        {
            float c[4][4];
#pragma unroll
            for (int j = 0; j < 4; j++)
#pragma unroll
                for (int cc = 0; cc < 4; cc++) c[j][cc] = 0.f;

#pragma unroll
            for (int ks = 0; ks < 24; ks++) {
                float4 a = *(const float4*)&sm.Qf[((mtile * 24 + ks) * 32 + lane) * 4];
#pragma unroll
                for (int j = 0; j < 4; j++) {
                    float2 bb = *(const float2*)&sm.Kf[(((ntb + j) * 24 + ks) * 32 + lane) * 2];
                    mma_tf32(c[j][0], c[j][1], c[j][2], c[j][3],
                             a.x, a.y, a.z, a.w, bb.x, bb.y);
                }
            }

            const bool diag = (kt == qt);
            const int r0 = mtile * 16 + (lane >> 2);
#pragma unroll
            for (int j = 0; j < 4; j++) {
                int col = (ntb + j) * 8 + (lane & 3) * 2;
                int ki0 = kt * BKT + col;
                float s0 = c[j][0] * SM_SCALE, s1 = c[j][1] * SM_SCALE;
                float s2 = c[j][2] * SM_SCALE, s3 = c[j][3] * SM_SCALE;
                if (diag) {
                    int qi0 = qt * BQ + r0;
                    int qi1 = qi0 + 8;
                    if (ki0     > qi0) s0 = -1e9f;
                    if (ki0 + 1 > qi0) s1 = -1e9f;
                    if (ki0     > qi1) s2 = -1e9f;
                    if (ki0 + 1 > qi1) s3 = -1e9f;
                }
                *(float2*)&sm.P[r0][col]     = make_float2(s0, s1);
                *(float2*)&sm.P[r0 + 8][col] = make_float2(s2, s3);
            }
        }
        __syncthreads();

        // ---- online softmax ----
        {
            float sv[16];
            float tmax = -1e30f;
#pragma unroll
            for (int jj = 0; jj < 16; jj++) {
                sv[jj] = sm.P[srow][squad * 16 + jj];
                tmax = fmaxf(tmax, sv[jj]);
            }
            tmax = fmaxf(tmax, __shfl_xor_sync(0xffffffffu, tmax, 1));
            tmax = fmaxf(tmax, __shfl_xor_sync(0xffffffffu, tmax, 2));
            float mnew = fmaxf(m, tmax);
            float al   = __expf(m - mnew);
            float ps = 0.f;
#pragma unroll
            for (int jj = 0; jj < 16; jj++) {
                float p = __expf(sv[jj] - mnew);
                sm.P[srow][squad * 16 + jj] = p;
                ps += p;
            }
            ps += __shfl_xor_sync(0xffffffffu, ps, 1);
            ps += __shfl_xor_sync(0xffffffffu, ps, 2);
            l = l * al + ps;
            m = mnew;
            if (squad == 0) sm.alpha[srow] = al;
        }
        __syncthreads();

        // ---- O = O*alpha + P @ V (fp32) ----
        {
            float al[4];
#pragma unroll
            for (int i = 0; i < 4; i++) al[i] = sm.alpha[ty * 4 + i];
#pragma unroll
            for (int i = 0; i < 4; i++)
#pragma unroll
                for (int j = 0; j < 8; j++) acc[i][j] *= al[i];

#pragma unroll 2
            for (int kj = 0; kj < BKT; kj++) {
                float4 v0 = *(const float4*)&sm.V[kj][tx * 8];
                float4 v1 = *(const float4*)&sm.V[kj][tx * 8 + 4];
                float pv[4];
#pragma unroll
                for (int i = 0; i < 4; i++) pv[i] = sm.P[ty * 4 + i][kj];
#pragma unroll
                for (int i = 0; i < 4; i++) {
                    acc[i][0] += pv[i] * v0.x;
                    acc[i][1] += pv[i] * v0.y;
                    acc[i][2] += pv[i] * v0.z;
                    acc[i][3] += pv[i] * v0.w;
                    acc[i][4] += pv[i] * v1.x;
                    acc[i][5] += pv[i] * v1.y;
                    acc[i][6] += pv[i] * v1.z;
                    acc[i][7] += pv[i] * v1.w;
                }
            }
        }
    }

    if (squad == 0) sm.invl[srow] = 1.f / l;
    __syncthreads();

#pragma unroll
    for (int i = 0; i < 4; i++) {
        float sc = sm.invl[ty * 4 + i];
        int tokq = qb + ty * 4 + i;
#pragma unroll
        for (int j = 0; j < 8; j++)
            out[(size_t)tokq * (NH * VD) + h * VD + tx * 8 + j] = acc[i][j] * sc;
    }
}

// ---------------------------------------------------------------------------
// Launch
// ---------------------------------------------------------------------------
static void launch_gemm(const float* A, const float* B, float* C,
                        int M, int N, int K)
{
    dim3 grid((N + 127) / 128, (M + 127) / 128);
    tf32_gemm_kernel<<<grid, 256>>>(A, B, C, M, N, K);
}

extern "C" void kernel_launch(void* const* d_in, const int* in_sizes, int n_in,
                              void* d_out, int out_size)
{
    const float* x         = (const float*)d_in[0];
    const float* W_cq      = (const float*)d_in[1];
    const float* q_scale   = (const float*)d_in[2];
    const float* W_dq_nope = (const float*)d_in[3];
    const float* W_dq_rope = (const float*)d_in[4];
    const float* W_ckv     = (const float*)d_in[5];
    const float* kv_scale  = (const float*)d_in[6];
    const float* W_dk_nope = (const float*)d_in[7];
    const float* W_dv      = (const float*)d_in[8];
    const float* W_krope   = (const float*)d_in[9];
    const float* W_o       = (const float*)d_in[10];
    float* out = (float*)d_out;

    float *cq, *qn, *qr, *ckv, *kn, *vv, *kr, *att, *ctab, *stab;
    cudaGetSymbolAddress((void**)&cq,  g_cq);
    cudaGetSymbolAddress((void**)&qn,  g_qnope);
    cudaGetSymbolAddress((void**)&qr,  g_qrope);
    cudaGetSymbolAddress((void**)&ckv, g_ckv);
    cudaGetSymbolAddress((void**)&kn,  g_knope);
    cudaGetSymbolAddress((void**)&vv,  g_v);
    cudaGetSymbolAddress((void**)&kr,  g_krope);
    cudaGetSymbolAddress((void**)&att, g_attn);
    cudaGetSymbolAddress((void**)&ctab, g_ctab);
    cudaGetSymbolAddress((void**)&stab, g_stab);

    // RoPE tables
    rope_table_kernel<<<(S * 32 + 255) / 256, 256>>>(ctab, stab);

    // Q path
    launch_gemm(x, W_cq, cq, T, QR, H);
    rmsnorm_kernel<<<T, 256>>>(cq, q_scale, QR);
    launch_gemm(cq, W_dq_nope, qn, T, NH * NOPE, QR);
    launch_gemm(cq, W_dq_rope, qr, T, NH * ROPE, QR);
    rope_q_kernel<<<(T * NH * 32 + 255) / 256, 256>>>(qr, ctab, stab);

    // KV path
    launch_gemm(x, W_ckv, ckv, T, KVR, H);
    rmsnorm_kernel<<<T, 256>>>(ckv, kv_scale, KVR);
    launch_gemm(ckv, W_dk_nope, kn, T, NH * NOPE, KVR);
    launch_gemm(ckv, W_dv, vv, T, NH * VD, KVR);
    launch_gemm(x, W_krope, kr, T, ROPE, H);
    rope_k_kernel<<<(T * 32 + 255) / 256, 256>>>(kr, ctab, stab);

    // Attention
    cudaFuncSetAttribute((const void*)attn_kernel,
                         cudaFuncAttributeMaxDynamicSharedMemorySize,
                         (int)sizeof(AttnSmem));
    attn_kernel<<<dim3(S / BQ, NH, BB), 256, sizeof(AttnSmem)>>>(qn, qr, kn, kr, vv, att);

    // Output projection
    launch_gemm(att, W_o, out, T, H, NH * VD);
}

// round 5
// speedup vs baseline: 3.1753x; 1.2757x over previous
#include <cuda_runtime.h>
#include <math.h>
#include <stdint.h>

// ---------------------------------------------------------------------------
// Problem constants
// ---------------------------------------------------------------------------
constexpr int H    = 2048;
constexpr int NH   = 16;
constexpr int NOPE = 128;
constexpr int ROPE = 64;
constexpr int VD   = 128;
constexpr int QR   = 1024;
constexpr int KVR  = 512;
constexpr int BB   = 2;       // batch
constexpr int S    = 2048;    // seq len
constexpr int T    = BB * S;  // 4096 tokens
constexpr float EPS = 1e-6f;
constexpr float SM_SCALE = 0.07216878364870323f; // 1/sqrt(192)

// ---------------------------------------------------------------------------
// Device scratch (allocation-free rule: __device__ globals)
// ---------------------------------------------------------------------------
__device__ float g_cq   [T * QR];
__device__ float g_qnope[T * NH * NOPE];
__device__ float g_qrope[T * NH * ROPE];
__device__ float g_ckv  [T * KVR];
__device__ float g_knope[T * NH * NOPE];
__device__ float g_v    [T * NH * VD];
__device__ float g_krope[T * ROPE];
__device__ float g_attn [T * NH * VD];
__device__ float g_ctab [S * (ROPE / 2)];
__device__ float g_stab [S * (ROPE / 2)];

// ---------------------------------------------------------------------------
// tf32 helpers
// ---------------------------------------------------------------------------
__device__ __forceinline__ float to_tf32(float x) {
    uint32_t u;
    asm("cvt.rna.tf32.f32 %0, %1;" : "=r"(u) : "f"(x));
    return __uint_as_float(u);
}
__device__ __forceinline__ float4 to_tf32x4(float4 v) {
    return make_float4(to_tf32(v.x), to_tf32(v.y), to_tf32(v.z), to_tf32(v.w));
}

__device__ __forceinline__ void mma_tf32(float& c0, float& c1, float& c2, float& c3,
                                         float a0, float a1, float a2, float a3,
                                         float b0, float b1)
{
    uint32_t ua0 = __float_as_uint(a0), ua1 = __float_as_uint(a1);
    uint32_t ua2 = __float_as_uint(a2), ua3 = __float_as_uint(a3);
    uint32_t ub0 = __float_as_uint(b0), ub1 = __float_as_uint(b1);
    asm volatile(
        "mma.sync.aligned.m16n8k8.row.col.f32.tf32.tf32.f32 "
        "{%0,%1,%2,%3}, {%4,%5,%6,%7}, {%8,%9}, {%0,%1,%2,%3};\n"
        : "+f"(c0), "+f"(c1), "+f"(c2), "+f"(c3)
        : "r"(ua0), "r"(ua1), "r"(ua2), "r"(ua3), "r"(ub0), "r"(ub1));
}

// Fragment-order smem stores used by the ATTENTION QK^T stage only.
template<int KSTEPS>
__device__ __forceinline__ void st_afrag(float* F, int m, int k, float4 v) {
    float* dst = F + (((m >> 4) * KSTEPS + (k >> 3)) * 32 + (m & 7) * 4 + (k & 3)) * 4
                   + ((m >> 3) & 1) + (((k >> 2) & 1) << 1);
    dst[0]  = to_tf32(v.x);
    dst[4]  = to_tf32(v.y);
    dst[8]  = to_tf32(v.z);
    dst[12] = to_tf32(v.w);
}
template<int KSTEPS>
__device__ __forceinline__ void st_bfrag_kvar(float* F, int r, int d, float4 v) {
    float* dst = F + (((r >> 3) * KSTEPS + (d >> 3)) * 32 + (r & 7) * 4 + (d & 3)) * 2
                   + ((d >> 2) & 1);
    dst[0] = to_tf32(v.x);
    dst[2] = to_tf32(v.y);
    dst[4] = to_tf32(v.z);
    dst[6] = to_tf32(v.w);
}

// ---------------------------------------------------------------------------
// tf32 tensor-core GEMM (proven): C[M,N] = A[M,K] @ B[K,N].
// 128x128 tile, BK=16, 256 threads, warp tile 64x32, double-buffered smem.
// ---------------------------------------------------------------------------
constexpr int AS_STRIDE = 20;
constexpr int BS_STRIDE = 136;

__global__ void __launch_bounds__(256)
tf32_gemm_kernel(const float* __restrict__ A, const float* __restrict__ B,
                 float* __restrict__ C, int M, int N, int K)
{
    __shared__ float As[2][128][AS_STRIDE];
    __shared__ float Bs[2][16][BS_STRIDE];

    const int tid  = threadIdx.x;
    const int lane = tid & 31;
    const int warp = tid >> 5;
    const int qid  = lane >> 2;
    const int rid  = lane & 3;
    const int wr   = (warp >> 2) * 64;
    const int wc   = (warp & 3) * 32;

    const int rowBase = blockIdx.y * 128;
    const int colBase = blockIdx.x * 128;

    const int ar0 = tid >> 2;
    const int ar1 = ar0 + 64;
    const int ac  = (tid & 3) * 4;
    const int bk0 = tid >> 5;
    const int bk1 = bk0 + 8;
    const int bn  = (tid & 31) * 4;
    const int gn  = colBase + bn;
    const bool bok = (gn < N);

    float acc[4][4][4];
#pragma unroll
    for (int i = 0; i < 4; i++)
#pragma unroll
        for (int j = 0; j < 4; j++)
#pragma unroll
            for (int c = 0; c < 4; c++) acc[i][j][c] = 0.f;

    const int nt = K / 16;
    float4 ra0, ra1, rb0, rb1;

    ra0 = *(const float4*)&A[(size_t)(rowBase + ar0) * K + ac];
    ra1 = *(const float4*)&A[(size_t)(rowBase + ar1) * K + ac];
    rb0 = bok ? *(const float4*)&B[(size_t)bk0 * N + gn] : make_float4(0,0,0,0);
    rb1 = bok ? *(const float4*)&B[(size_t)bk1 * N + gn] : make_float4(0,0,0,0);
    *(float4*)&As[0][ar0][ac] = to_tf32x4(ra0);
    *(float4*)&As[0][ar1][ac] = to_tf32x4(ra1);
    *(float4*)&Bs[0][bk0][bn] = to_tf32x4(rb0);
    *(float4*)&Bs[0][bk1][bn] = to_tf32x4(rb1);
    __syncthreads();

    for (int t = 0; t < nt; t++) {
        const int buf = t & 1;

        if (t + 1 < nt) {
            const int k0 = (t + 1) * 16;
            ra0 = *(const float4*)&A[(size_t)(rowBase + ar0) * K + k0 + ac];
            ra1 = *(const float4*)&A[(size_t)(rowBase + ar1) * K + k0 + ac];
            rb0 = bok ? *(const float4*)&B[(size_t)(k0 + bk0) * N + gn] : make_float4(0,0,0,0);
            rb1 = bok ? *(const float4*)&B[(size_t)(k0 + bk1) * N + gn] : make_float4(0,0,0,0);
        }

#pragma unroll
        for (int ks = 0; ks < 16; ks += 8) {
            float a[4][4], b[4][2];
#pragma unroll
            for (int i = 0; i < 4; i++) {
                const float* p0 = &As[buf][wr + i * 16 + qid][ks + rid];
                const float* p1 = &As[buf][wr + i * 16 + qid + 8][ks + rid];
                a[i][0] = p0[0];
                a[i][1] = p1[0];
                a[i][2] = p0[4];
                a[i][3] = p1[4];
            }
#pragma unroll
            for (int j = 0; j < 4; j++) {
                b[j][0] = Bs[buf][ks + rid][wc + j * 8 + qid];
                b[j][1] = Bs[buf][ks + rid + 4][wc + j * 8 + qid];
            }
#pragma unroll
            for (int i = 0; i < 4; i++)
#pragma unroll
                for (int j = 0; j < 4; j++)
                    mma_tf32(acc[i][j][0], acc[i][j][1], acc[i][j][2], acc[i][j][3],
                             a[i][0], a[i][1], a[i][2], a[i][3],
                             b[j][0], b[j][1]);
        }

        if (t + 1 < nt) {
            const int nb = (t + 1) & 1;
            *(float4*)&As[nb][ar0][ac] = to_tf32x4(ra0);
            *(float4*)&As[nb][ar1][ac] = to_tf32x4(ra1);
            *(float4*)&Bs[nb][bk0][bn] = to_tf32x4(rb0);
            *(float4*)&Bs[nb][bk1][bn] = to_tf32x4(rb1);
        }
        __syncthreads();
    }

#pragma unroll
    for (int i = 0; i < 4; i++) {
        const int r0 = rowBase + wr + i * 16 + qid;
#pragma unroll
        for (int j = 0; j < 4; j++) {
            const int col = colBase + wc + j * 8 + rid * 2;
            if (col < N) {
                *(float2*)&C[(size_t)r0 * N + col]       = make_float2(acc[i][j][0], acc[i][j][1]);
                *(float2*)&C[(size_t)(r0 + 8) * N + col] = make_float2(acc[i][j][2], acc[i][j][3]);
            }
        }
    }
}

// ---------------------------------------------------------------------------
// RMSNorm (in place)
// ---------------------------------------------------------------------------
__global__ void rmsnorm_kernel(float* __restrict__ x,
                               const float* __restrict__ scale, int D)
{
    __shared__ float red[32];
    float* p = x + (size_t)blockIdx.x * D;

    float ss = 0.f;
    for (int d = threadIdx.x; d < D; d += blockDim.x) {
        float v = p[d];
        ss += v * v;
    }
#pragma unroll
    for (int o = 16; o; o >>= 1) ss += __shfl_xor_sync(0xffffffffu, ss, o);
    if ((threadIdx.x & 31) == 0) red[threadIdx.x >> 5] = ss;
    __syncthreads();
    if (threadIdx.x < 32) {
        float v = (threadIdx.x < (blockDim.x >> 5)) ? red[threadIdx.x] : 0.f;
#pragma unroll
        for (int o = 16; o; o >>= 1) v += __shfl_xor_sync(0xffffffffu, v, o);
        if (threadIdx.x == 0) red[0] = v;
    }
    __syncthreads();
    float inv = rsqrtf(red[0] / (float)D + EPS);
    for (int d = threadIdx.x; d < D; d += blockDim.x)
        p[d] = p[d] * inv * scale[d];
}

// ---------------------------------------------------------------------------
// RoPE tables / application
// ---------------------------------------------------------------------------
__global__ void rope_table_kernel(float* __restrict__ ctab, float* __restrict__ stab)
{
    int idx = blockIdx.x * blockDim.x + threadIdx.x;
    if (idx >= S * (ROPE / 2)) return;
    int i = idx % (ROPE / 2);
    int s = idx / (ROPE / 2);
    float freq = (float)pow(10000.0, -((double)(2 * i)) / (double)ROPE);
    float ang  = (float)s * freq;
    double a   = (double)ang;
    ctab[idx] = (float)cos(a);
    stab[idx] = (float)sin(a);
}

__global__ void rope_q_kernel(float* __restrict__ q,
                              const float* __restrict__ ctab,
                              const float* __restrict__ stab)
{
    int idx = blockIdx.x * blockDim.x + threadIdx.x;
    if (idx >= T * NH * (ROPE / 2)) return;
    int i   = idx & 31;
    int rem = idx >> 5;
    int h   = rem & (NH - 1);
    int tok = rem >> 4;
    int s   = tok & (S - 1);
    float c  = ctab[s * 32 + i];
    float sn = stab[s * 32 + i];
    float* p = q + (size_t)tok * (NH * ROPE) + h * ROPE + 2 * i;
    float x1 = p[0], x2 = p[1];
    p[0] = x1 * c - x2 * sn;
    p[1] = x1 * sn + x2 * c;
}

__global__ void rope_k_kernel(float* __restrict__ k,
                              const float* __restrict__ ctab,
                              const float* __restrict__ stab)
{
    int idx = blockIdx.x * blockDim.x + threadIdx.x;
    if (idx >= T * (ROPE / 2)) return;
    int i   = idx & 31;
    int tok = idx >> 5;
    int s   = tok & (S - 1);
    float c  = ctab[s * 32 + i];
    float sn = stab[s * 32 + i];
    float* p = k + (size_t)tok * ROPE + 2 * i;
    float x1 = p[0], x2 = p[1];
    p[0] = (x1 * c - x2 * sn) * 0.0625f;   // /NH folded in
    p[1] = (x1 * sn + x2 * c) * 0.0625f;
}

// ---------------------------------------------------------------------------
// Flash attention: QK^T AND PV on tf32 mma. PV reads P (stride 68 == 4 mod 32)
// and V (stride 136 == 8 mod 32) directly from row-major smem — both operand
// access patterns are conflict-free scalar LDS. Softmax writes tf32 P in place.
// ---------------------------------------------------------------------------
constexpr int BQ  = 64;
constexpr int BKT = 64;
constexpr int VSTR = 136;  // V row stride: rid*8+qid covers all 32 banks
constexpr int PSTR = 68;   // P row stride: qid*4+rid covers all 32 banks

struct AttnSmem {
    float Qf[4 * 24 * 32 * 4];   // QK A-frag layout
    float Kf[8 * 24 * 32 * 2];   // QK B-frag layout
    float V[BKT][VSTR];
    float P[BQ][PSTR];
    float alpha[BQ];
    float invl[BQ];
};

__global__ void __launch_bounds__(256)
attn_kernel(const float* __restrict__ qn, const float* __restrict__ qr,
            const float* __restrict__ kn, const float* __restrict__ kr,
            const float* __restrict__ v,  float* __restrict__ out)
{
    extern __shared__ char smraw[];
    AttnSmem& sm = *reinterpret_cast<AttnSmem*>(smraw);

    const int qt = blockIdx.x;
    const int h  = blockIdx.y;
    const int b  = blockIdx.z;
    const int tid = threadIdx.x;
    const int lane = tid & 31;
    const int warp = tid >> 5;
    const int qid  = lane >> 2;
    const int rid  = lane & 3;
    const int qb = b * S + qt * BQ;

    // QK warp mapping: rows (warp&3)*16, cols (warp>>2)*32
    const int mtile = warp & 3;
    const int ntb   = (warp >> 2) * 4;
    // PV warp mapping: rows mtile*16 (+qid, +8), cols (warp>>2)*64
    const int row0 = mtile * 16 + qid;
    const int nbv  = (warp >> 2) * 64;

    // ---- load Q tile into fragment layout ----
    for (int idx = tid; idx < BQ * 32; idx += 256) {
        int r = idx >> 5, dq = (idx & 31) * 4;
        float4 vq = *(const float4*)&qn[(size_t)(qb + r) * (NH * NOPE) + h * NOPE + dq];
        st_afrag<24>(sm.Qf, r, dq, vq);
    }
    for (int idx = tid; idx < BQ * 16; idx += 256) {
        int r = idx >> 4, dq = (idx & 15) * 4;
        float4 vq = *(const float4*)&qr[(size_t)(qb + r) * (NH * ROPE) + h * ROPE + dq];
        st_afrag<24>(sm.Qf, r, 128 + dq, vq);
    }

    const int srow = tid >> 2, squad = tid & 3;   // softmax mapping (64 x 4)

    float m = -1e30f, l = 0.f;
    float acc[8][4];                               // PV accumulators (mma C layout)
#pragma unroll
    for (int j = 0; j < 8; j++)
#pragma unroll
        for (int c = 0; c < 4; c++) acc[j][c] = 0.f;

    const int nkt = qt + 1;                        // causal tile skip
    for (int kt = 0; kt < nkt; kt++) {
        const int kbT = b * S + kt * BKT;
        __syncthreads();

        // ---- load K tile (frag layout) + V tile (raw, tf32-rounded) ----
        for (int idx = tid; idx < BKT * 32; idx += 256) {
            int r = idx >> 5, dq = (idx & 31) * 4;
            float4 vk = *(const float4*)&kn[(size_t)(kbT + r) * (NH * NOPE) + h * NOPE + dq];
            st_bfrag_kvar<24>(sm.Kf, r, dq, vk);
        }
        for (int idx = tid; idx < BKT * 16; idx += 256) {
            int r = idx >> 4, dq = (idx & 15) * 4;
            float4 vk = *(const float4*)&kr[(size_t)(kbT + r) * ROPE + dq];
            st_bfrag_kvar<24>(sm.Kf, r, 128 + dq, vk);
        }
        for (int idx = tid; idx < BKT * 32; idx += 256) {
            int r = idx >> 5, dq = (idx & 31) * 4;
            float4 vv4 = *(const float4*)&v[(size_t)(kbT + r) * (NH * VD) + h * VD + dq];
            *(float4*)&sm.V[r][dq] = to_tf32x4(vv4);
        }
        __syncthreads();

        // ---- scores via tf32 mma: warp computes 16x32 ----
        {
            float c[4][4];
#pragma unroll
            for (int j = 0; j < 4; j++)
#pragma unroll
                for (int cc = 0; cc < 4; cc++) c[j][cc] = 0.f;

#pragma unroll
            for (int ks = 0; ks < 24; ks++) {
                float4 a = *(const float4*)&sm.Qf[((mtile * 24 + ks) * 32 + lane) * 4];
#pragma unroll
                for (int j = 0; j < 4; j++) {
                    float2 bb = *(const float2*)&sm.Kf[(((ntb + j) * 24 + ks) * 32 + lane) * 2];
                    mma_tf32(c[j][0], c[j][1], c[j][2], c[j][3],
                             a.x, a.y, a.z, a.w, bb.x, bb.y);
                }
            }

            const bool diag = (kt == qt);
            const int r0 = mtile * 16 + qid;
#pragma unroll
            for (int j = 0; j < 4; j++) {
                int col = (ntb + j) * 8 + rid * 2;
                int ki0 = kt * BKT + col;
                float s0 = c[j][0] * SM_SCALE, s1 = c[j][1] * SM_SCALE;
                float s2 = c[j][2] * SM_SCALE, s3 = c[j][3] * SM_SCALE;
                if (diag) {
                    int qi0 = qt * BQ + r0;
                    int qi1 = qi0 + 8;
                    if (ki0     > qi0) s0 = -1e9f;
                    if (ki0 + 1 > qi0) s1 = -1e9f;
                    if (ki0     > qi1) s2 = -1e9f;
                    if (ki0 + 1 > qi1) s3 = -1e9f;
                }
                *(float2*)&sm.P[r0][col]     = make_float2(s0, s1);
                *(float2*)&sm.P[r0 + 8][col] = make_float2(s2, s3);
            }
        }
        __syncthreads();

        // ---- online softmax (l summed in fp32; P stored as tf32 for mma) ----
        {
            float sv[16];
            float tmax = -1e30f;
#pragma unroll
            for (int jj = 0; jj < 16; jj++) {
                sv[jj] = sm.P[srow][squad * 16 + jj];
                tmax = fmaxf(tmax, sv[jj]);
            }
            tmax = fmaxf(tmax, __shfl_xor_sync(0xffffffffu, tmax, 1));
            tmax = fmaxf(tmax, __shfl_xor_sync(0xffffffffu, tmax, 2));
            float mnew = fmaxf(m, tmax);
            float al   = __expf(m - mnew);
            float ps = 0.f;
#pragma unroll
            for (int jj = 0; jj < 16; jj++) {
                float p = __expf(sv[jj] - mnew);
                sm.P[srow][squad * 16 + jj] = to_tf32(p);
                ps += p;
            }
            ps += __shfl_xor_sync(0xffffffffu, ps, 1);
            ps += __shfl_xor_sync(0xffffffffu, ps, 2);
            l = l * al + ps;
            m = mnew;
            if (squad == 0) sm.alpha[srow] = al;
        }
        __syncthreads();

        // ---- O = O*alpha + P @ V via tf32 mma (conflict-free raw-smem reads) ----
        {
            const float al0 = sm.alpha[row0];
            const float al1 = sm.alpha[row0 + 8];
#pragma unroll
            for (int j = 0; j < 8; j++) {
                acc[j][0] *= al0; acc[j][1] *= al0;
                acc[j][2] *= al1; acc[j][3] *= al1;
            }
#pragma unroll
            for (int ks = 0; ks < 8; ks++) {
                const float a0 = sm.P[row0]    [ks * 8 + rid];
                const float a1 = sm.P[row0 + 8][ks * 8 + rid];
                const float a2 = sm.P[row0]    [ks * 8 + rid + 4];
                const float a3 = sm.P[row0 + 8][ks * 8 + rid + 4];
#pragma unroll
                for (int j = 0; j < 8; j++) {
                    const float b0 = sm.V[ks * 8 + rid]    [nbv + j * 8 + qid];
                    const float b1 = sm.V[ks * 8 + rid + 4][nbv + j * 8 + qid];
                    mma_tf32(acc[j][0], acc[j][1], acc[j][2], acc[j][3],
                             a0, a1, a2, a3, b0, b1);
                }
            }
        }
    }

    if (squad == 0) sm.invl[srow] = 1.f / l;
    __syncthreads();

    // ---- epilogue: scale by 1/l, write out (mma C layout) ----
    {
        const float il0 = sm.invl[row0];
        const float il1 = sm.invl[row0 + 8];
        const int tok0 = qb + row0;
        const int tok1 = tok0 + 8;
#pragma unroll
        for (int j = 0; j < 8; j++) {
            const int col = nbv + j * 8 + rid * 2;
            *(float2*)&out[(size_t)tok0 * (NH * VD) + h * VD + col] =
                make_float2(acc[j][0] * il0, acc[j][1] * il0);
            *(float2*)&out[(size_t)tok1 * (NH * VD) + h * VD + col] =
                make_float2(acc[j][2] * il1, acc[j][3] * il1);
        }
    }
}

// ---------------------------------------------------------------------------
// Launch
// ---------------------------------------------------------------------------
static void launch_gemm(const float* A, const float* B, float* C,
                        int M, int N, int K)
{
    dim3 grid((N + 127) / 128, (M + 127) / 128);
    tf32_gemm_kernel<<<grid, 256>>>(A, B, C, M, N, K);
}

extern "C" void kernel_launch(void* const* d_in, const int* in_sizes, int n_in,
                              void* d_out, int out_size)
{
    const float* x         = (const float*)d_in[0];
    const float* W_cq      = (const float*)d_in[1];
    const float* q_scale   = (const float*)d_in[2];
    const float* W_dq_nope = (const float*)d_in[3];
    const float* W_dq_rope = (const float*)d_in[4];
    const float* W_ckv     = (const float*)d_in[5];
    const float* kv_scale  = (const float*)d_in[6];
    const float* W_dk_nope = (const float*)d_in[7];
    const float* W_dv      = (const float*)d_in[8];
    const float* W_krope   = (const float*)d_in[9];
    const float* W_o       = (const float*)d_in[10];
    float* out = (float*)d_out;

    float *cq, *qn, *qr, *ckv, *kn, *vv, *kr, *att, *ctab, *stab;
    cudaGetSymbolAddress((void**)&cq,  g_cq);
    cudaGetSymbolAddress((void**)&qn,  g_qnope);
    cudaGetSymbolAddress((void**)&qr,  g_qrope);
    cudaGetSymbolAddress((void**)&ckv, g_ckv);
    cudaGetSymbolAddress((void**)&kn,  g_knope);
    cudaGetSymbolAddress((void**)&vv,  g_v);
    cudaGetSymbolAddress((void**)&kr,  g_krope);
    cudaGetSymbolAddress((void**)&att, g_attn);
    cudaGetSymbolAddress((void**)&ctab, g_ctab);
    cudaGetSymbolAddress((void**)&stab, g_stab);

    // RoPE tables
    rope_table_kernel<<<(S * 32 + 255) / 256, 256>>>(ctab, stab);

    // Q path
    launch_gemm(x, W_cq, cq, T, QR, H);
    rmsnorm_kernel<<<T, 256>>>(cq, q_scale, QR);
    launch_gemm(cq, W_dq_nope, qn, T, NH * NOPE, QR);
    launch_gemm(cq, W_dq_rope, qr, T, NH * ROPE, QR);
    rope_q_kernel<<<(T * NH * 32 + 255) / 256, 256>>>(qr, ctab, stab);

    // KV path
    launch_gemm(x, W_ckv, ckv, T, KVR, H);
    rmsnorm_kernel<<<T, 256>>>(ckv, kv_scale, KVR);
    launch_gemm(ckv, W_dk_nope, kn, T, NH * NOPE, KVR);
    launch_gemm(ckv, W_dv, vv, T, NH * VD, KVR);
    launch_gemm(x, W_krope, kr, T, ROPE, H);
    rope_k_kernel<<<(T * 32 + 255) / 256, 256>>>(kr, ctab, stab);

    // Attention
    cudaFuncSetAttribute((const void*)attn_kernel,
                         cudaFuncAttributeMaxDynamicSharedMemorySize,
                         (int)sizeof(AttnSmem));
    attn_kernel<<<dim3(S / BQ, NH, BB), 256, sizeof(AttnSmem)>>>(qn, qr, kn, kr, vv, att);

    // Output projection
    launch_gemm(att, W_o, out, T, H, NH * VD);
}

// round 6
// speedup vs baseline: 3.5169x; 1.1076x over previous
#include <cuda_runtime.h>
#include <math.h>
#include <stdint.h>

// ---------------------------------------------------------------------------
// Problem constants
// ---------------------------------------------------------------------------
constexpr int H    = 2048;
constexpr int NH   = 16;
constexpr int NOPE = 128;
constexpr int ROPE = 64;
constexpr int VD   = 128;
constexpr int QR   = 1024;
constexpr int KVR  = 512;
constexpr int BB   = 2;       // batch
constexpr int S    = 2048;    // seq len
constexpr int T    = BB * S;  // 4096 tokens
constexpr float EPS = 1e-6f;
constexpr float SM_SCALE = 0.07216878364870323f; // 1/sqrt(192)

// ---------------------------------------------------------------------------
// Device scratch (allocation-free rule: __device__ globals)
// ---------------------------------------------------------------------------
__device__ float g_cq   [T * QR];
__device__ float g_qnope[T * NH * NOPE];
__device__ float g_qrope[T * NH * ROPE];
__device__ float g_ckv  [T * KVR];
__device__ float g_knope[T * NH * NOPE];
__device__ float g_v    [T * NH * VD];
__device__ float g_krope[T * ROPE];
__device__ float g_attn [T * NH * VD];
__device__ float g_ctab [S * (ROPE / 2)];
__device__ float g_stab [S * (ROPE / 2)];

// ---------------------------------------------------------------------------
// tf32 helpers
// ---------------------------------------------------------------------------
__device__ __forceinline__ float to_tf32(float x) {
    uint32_t u;
    asm("cvt.rna.tf32.f32 %0, %1;" : "=r"(u) : "f"(x));
    return __uint_as_float(u);
}
__device__ __forceinline__ float4 to_tf32x4(float4 v) {
    return make_float4(to_tf32(v.x), to_tf32(v.y), to_tf32(v.z), to_tf32(v.w));
}

__device__ __forceinline__ void mma_tf32(float& c0, float& c1, float& c2, float& c3,
                                         float a0, float a1, float a2, float a3,
                                         float b0, float b1)
{
    uint32_t ua0 = __float_as_uint(a0), ua1 = __float_as_uint(a1);
    uint32_t ua2 = __float_as_uint(a2), ua3 = __float_as_uint(a3);
    uint32_t ub0 = __float_as_uint(b0), ub1 = __float_as_uint(b1);
    asm volatile(
        "mma.sync.aligned.m16n8k8.row.col.f32.tf32.tf32.f32 "
        "{%0,%1,%2,%3}, {%4,%5,%6,%7}, {%8,%9}, {%0,%1,%2,%3};\n"
        : "+f"(c0), "+f"(c1), "+f"(c2), "+f"(c3)
        : "r"(ua0), "r"(ua1), "r"(ua2), "r"(ua3), "r"(ub0), "r"(ub1));
}

// Fragment-order smem stores used by the ATTENTION QK^T stage only.
template<int KSTEPS>
__device__ __forceinline__ void st_afrag(float* F, int m, int k, float4 v) {
    float* dst = F + (((m >> 4) * KSTEPS + (k >> 3)) * 32 + (m & 7) * 4 + (k & 3)) * 4
                   + ((m >> 3) & 1) + (((k >> 2) & 1) << 1);
    dst[0]  = to_tf32(v.x);
    dst[4]  = to_tf32(v.y);
    dst[8]  = to_tf32(v.z);
    dst[12] = to_tf32(v.w);
}
template<int KSTEPS>
__device__ __forceinline__ void st_bfrag_kvar(float* F, int r, int d, float4 v) {
    float* dst = F + (((r >> 3) * KSTEPS + (d >> 3)) * 32 + (r & 7) * 4 + (d & 3)) * 2
                   + ((d >> 2) & 1);
    dst[0] = to_tf32(v.x);
    dst[2] = to_tf32(v.y);
    dst[4] = to_tf32(v.z);
    dst[6] = to_tf32(v.w);
}

// ---------------------------------------------------------------------------
// tf32 tensor-core GEMM (proven): C[M,N] = A[M,K] @ B[K,N].
// 128x128 tile, BK=16, 256 threads, warp tile 64x32, double-buffered smem.
// ---------------------------------------------------------------------------
constexpr int AS_STRIDE = 20;
constexpr int BS_STRIDE = 136;

__global__ void __launch_bounds__(256)
tf32_gemm_kernel(const float* __restrict__ A, const float* __restrict__ B,
                 float* __restrict__ C, int M, int N, int K)
{
    __shared__ float As[2][128][AS_STRIDE];
    __shared__ float Bs[2][16][BS_STRIDE];

    const int tid  = threadIdx.x;
    const int lane = tid & 31;
    const int warp = tid >> 5;
    const int qid  = lane >> 2;
    const int rid  = lane & 3;
    const int wr   = (warp >> 2) * 64;
    const int wc   = (warp & 3) * 32;

    const int rowBase = blockIdx.y * 128;
    const int colBase = blockIdx.x * 128;

    const int ar0 = tid >> 2;
    const int ar1 = ar0 + 64;
    const int ac  = (tid & 3) * 4;
    const int bk0 = tid >> 5;
    const int bk1 = bk0 + 8;
    const int bn  = (tid & 31) * 4;
    const int gn  = colBase + bn;
    const bool bok = (gn < N);

    float acc[4][4][4];
#pragma unroll
    for (int i = 0; i < 4; i++)
#pragma unroll
        for (int j = 0; j < 4; j++)
#pragma unroll
            for (int c = 0; c < 4; c++) acc[i][j][c] = 0.f;

    const int nt = K / 16;
    float4 ra0, ra1, rb0, rb1;

    ra0 = *(const float4*)&A[(size_t)(rowBase + ar0) * K + ac];
    ra1 = *(const float4*)&A[(size_t)(rowBase + ar1) * K + ac];
    rb0 = bok ? *(const float4*)&B[(size_t)bk0 * N + gn] : make_float4(0,0,0,0);
    rb1 = bok ? *(const float4*)&B[(size_t)bk1 * N + gn] : make_float4(0,0,0,0);
    *(float4*)&As[0][ar0][ac] = to_tf32x4(ra0);
    *(float4*)&As[0][ar1][ac] = to_tf32x4(ra1);
    *(float4*)&Bs[0][bk0][bn] = to_tf32x4(rb0);
    *(float4*)&Bs[0][bk1][bn] = to_tf32x4(rb1);
    __syncthreads();

    for (int t = 0; t < nt; t++) {
        const int buf = t & 1;

        if (t + 1 < nt) {
            const int k0 = (t + 1) * 16;
            ra0 = *(const float4*)&A[(size_t)(rowBase + ar0) * K + k0 + ac];
            ra1 = *(const float4*)&A[(size_t)(rowBase + ar1) * K + k0 + ac];
            rb0 = bok ? *(const float4*)&B[(size_t)(k0 + bk0) * N + gn] : make_float4(0,0,0,0);
            rb1 = bok ? *(const float4*)&B[(size_t)(k0 + bk1) * N + gn] : make_float4(0,0,0,0);
        }

#pragma unroll
        for (int ks = 0; ks < 16; ks += 8) {
            float a[4][4], b[4][2];
#pragma unroll
            for (int i = 0; i < 4; i++) {
                const float* p0 = &As[buf][wr + i * 16 + qid][ks + rid];
                const float* p1 = &As[buf][wr + i * 16 + qid + 8][ks + rid];
                a[i][0] = p0[0];
                a[i][1] = p1[0];
                a[i][2] = p0[4];
                a[i][3] = p1[4];
            }
#pragma unroll
            for (int j = 0; j < 4; j++) {
                b[j][0] = Bs[buf][ks + rid][wc + j * 8 + qid];
                b[j][1] = Bs[buf][ks + rid + 4][wc + j * 8 + qid];
            }
#pragma unroll
            for (int i = 0; i < 4; i++)
#pragma unroll
                for (int j = 0; j < 4; j++)
                    mma_tf32(acc[i][j][0], acc[i][j][1], acc[i][j][2], acc[i][j][3],
                             a[i][0], a[i][1], a[i][2], a[i][3],
                             b[j][0], b[j][1]);
        }

        if (t + 1 < nt) {
            const int nb = (t + 1) & 1;
            *(float4*)&As[nb][ar0][ac] = to_tf32x4(ra0);
            *(float4*)&As[nb][ar1][ac] = to_tf32x4(ra1);
            *(float4*)&Bs[nb][bk0][bn] = to_tf32x4(rb0);
            *(float4*)&Bs[nb][bk1][bn] = to_tf32x4(rb1);
        }
        __syncthreads();
    }

#pragma unroll
    for (int i = 0; i < 4; i++) {
        const int r0 = rowBase + wr + i * 16 + qid;
#pragma unroll
        for (int j = 0; j < 4; j++) {
            const int col = colBase + wc + j * 8 + rid * 2;
            if (col < N) {
                *(float2*)&C[(size_t)r0 * N + col]       = make_float2(acc[i][j][0], acc[i][j][1]);
                *(float2*)&C[(size_t)(r0 + 8) * N + col] = make_float2(acc[i][j][2], acc[i][j][3]);
            }
        }
    }
}

// ---------------------------------------------------------------------------
// RMSNorm (in place)
// ---------------------------------------------------------------------------
__global__ void rmsnorm_kernel(float* __restrict__ x,
                               const float* __restrict__ scale, int D)
{
    __shared__ float red[32];
    float* p = x + (size_t)blockIdx.x * D;

    float ss = 0.f;
    for (int d = threadIdx.x; d < D; d += blockDim.x) {
        float v = p[d];
        ss += v * v;
    }
#pragma unroll
    for (int o = 16; o; o >>= 1) ss += __shfl_xor_sync(0xffffffffu, ss, o);
    if ((threadIdx.x & 31) == 0) red[threadIdx.x >> 5] = ss;
    __syncthreads();
    if (threadIdx.x < 32) {
        float v = (threadIdx.x < (blockDim.x >> 5)) ? red[threadIdx.x] : 0.f;
#pragma unroll
        for (int o = 16; o; o >>= 1) v += __shfl_xor_sync(0xffffffffu, v, o);
        if (threadIdx.x == 0) red[0] = v;
    }
    __syncthreads();
    float inv = rsqrtf(red[0] / (float)D + EPS);
    for (int d = threadIdx.x; d < D; d += blockDim.x)
        p[d] = p[d] * inv * scale[d];
}

// ---------------------------------------------------------------------------
// RoPE tables / application
// ---------------------------------------------------------------------------
__global__ void rope_table_kernel(float* __restrict__ ctab, float* __restrict__ stab)
{
    int idx = blockIdx.x * blockDim.x + threadIdx.x;
    if (idx >= S * (ROPE / 2)) return;
    int i = idx % (ROPE / 2);
    int s = idx / (ROPE / 2);
    float freq = (float)pow(10000.0, -((double)(2 * i)) / (double)ROPE);
    float ang  = (float)s * freq;
    double a   = (double)ang;
    ctab[idx] = (float)cos(a);
    stab[idx] = (float)sin(a);
}

__global__ void rope_q_kernel(float* __restrict__ q,
                              const float* __restrict__ ctab,
                              const float* __restrict__ stab)
{
    int idx = blockIdx.x * blockDim.x + threadIdx.x;
    if (idx >= T * NH * (ROPE / 2)) return;
    int i   = idx & 31;
    int rem = idx >> 5;
    int h   = rem & (NH - 1);
    int tok = rem >> 4;
    int s   = tok & (S - 1);
    float c  = ctab[s * 32 + i];
    float sn = stab[s * 32 + i];
    float* p = q + (size_t)tok * (NH * ROPE) + h * ROPE + 2 * i;
    float x1 = p[0], x2 = p[1];
    p[0] = x1 * c - x2 * sn;
    p[1] = x1 * sn + x2 * c;
}

__global__ void rope_k_kernel(float* __restrict__ k,
                              const float* __restrict__ ctab,
                              const float* __restrict__ stab)
{
    int idx = blockIdx.x * blockDim.x + threadIdx.x;
    if (idx >= T * (ROPE / 2)) return;
    int i   = idx & 31;
    int tok = idx >> 5;
    int s   = tok & (S - 1);
    float c  = ctab[s * 32 + i];
    float sn = stab[s * 32 + i];
    float* p = k + (size_t)tok * ROPE + 2 * i;
    float x1 = p[0], x2 = p[1];
    p[0] = (x1 * c - x2 * sn) * 0.0625f;   // /NH folded in
    p[1] = (x1 * sn + x2 * c) * 0.0625f;
}

// ---------------------------------------------------------------------------
// Flash attention: BQ=128 query tile, 512 threads (16 warps), single CTA/SM.
// QK^T and PV both on tf32 mma; conflict-free smem patterns as before.
// ---------------------------------------------------------------------------
constexpr int BQ  = 128;
constexpr int BKT = 64;
constexpr int VSTR = 136;  // V row stride: rid*8+qid covers all 32 banks
constexpr int PSTR = 68;   // P row stride: qid*4+rid covers all 32 banks

struct AttnSmem {
    float Qf[8 * 24 * 32 * 4];   // QK A-frag layout (8 mtiles x 24 ksteps)
    float Kf[8 * 24 * 32 * 2];   // QK B-frag layout (8 ntiles x 24 ksteps)
    float V[BKT][VSTR];
    float P[BQ][PSTR];
    float alpha[BQ];
    float invl[BQ];
};

__global__ void __launch_bounds__(512)
attn_kernel(const float* __restrict__ qn, const float* __restrict__ qr,
            const float* __restrict__ kn, const float* __restrict__ kr,
            const float* __restrict__ v,  float* __restrict__ out)
{
    extern __shared__ char smraw[];
    AttnSmem& sm = *reinterpret_cast<AttnSmem*>(smraw);

    const int qt = blockIdx.x;
    const int h  = blockIdx.y;
    const int b  = blockIdx.z;
    const int tid = threadIdx.x;
    const int lane = tid & 31;
    const int warp = tid >> 5;          // 0..15
    const int qid  = lane >> 2;
    const int rid  = lane & 3;
    const int qb = b * S + qt * BQ;

    // QK warp mapping: rows (warp&7)*16, cols (warp>>3)*32
    const int mtile = warp & 7;
    const int ntb   = (warp >> 3) * 4;
    // PV warp mapping: rows (warp&7)*16 (+qid, +8), cols (warp>>3)*64
    const int row0 = mtile * 16 + qid;
    const int nbv  = (warp >> 3) * 64;

    // ---- load Q tile [128 x 192] into fragment layout ----
    for (int idx = tid; idx < BQ * 32; idx += 512) {
        int r = idx >> 5, dq = (idx & 31) * 4;
        float4 vq = *(const float4*)&qn[(size_t)(qb + r) * (NH * NOPE) + h * NOPE + dq];
        st_afrag<24>(sm.Qf, r, dq, vq);
    }
    for (int idx = tid; idx < BQ * 16; idx += 512) {
        int r = idx >> 4, dq = (idx & 15) * 4;
        float4 vq = *(const float4*)&qr[(size_t)(qb + r) * (NH * ROPE) + h * ROPE + dq];
        st_afrag<24>(sm.Qf, r, 128 + dq, vq);
    }

    const int srow = tid >> 2, squad = tid & 3;   // softmax mapping (128 x 4)

    float m = -1e30f, l = 0.f;
    float acc[8][4];                               // PV accumulators (mma C layout)
#pragma unroll
    for (int j = 0; j < 8; j++)
#pragma unroll
        for (int c = 0; c < 4; c++) acc[j][c] = 0.f;

    const int nkt = 2 * qt + 2;                    // causal: keys up to (qt+1)*128
    for (int kt = 0; kt < nkt; kt++) {
        const int kbT = b * S + kt * BKT;
        __syncthreads();

        // ---- load K tile (frag layout) + V tile (raw, tf32-rounded) ----
        for (int idx = tid; idx < BKT * 32; idx += 512) {
            int r = idx >> 5, dq = (idx & 31) * 4;
            float4 vk = *(const float4*)&kn[(size_t)(kbT + r) * (NH * NOPE) + h * NOPE + dq];
            st_bfrag_kvar<24>(sm.Kf, r, dq, vk);
        }
        for (int idx = tid; idx < BKT * 16; idx += 512) {
            int r = idx >> 4, dq = (idx & 15) * 4;
            float4 vk = *(const float4*)&kr[(size_t)(kbT + r) * ROPE + dq];
            st_bfrag_kvar<24>(sm.Kf, r, 128 + dq, vk);
        }
        for (int idx = tid; idx < BKT * 32; idx += 512) {
            int r = idx >> 5, dq = (idx & 31) * 4;
            float4 vv4 = *(const float4*)&v[(size_t)(kbT + r) * (NH * VD) + h * VD + dq];
            *(float4*)&sm.V[r][dq] = to_tf32x4(vv4);
        }
        __syncthreads();

        // ---- scores via tf32 mma: each warp 16x32 of the 128x64 tile ----
        {
            float c[4][4];
#pragma unroll
            for (int j = 0; j < 4; j++)
#pragma unroll
                for (int cc = 0; cc < 4; cc++) c[j][cc] = 0.f;

#pragma unroll
            for (int ks = 0; ks < 24; ks++) {
                float4 a = *(const float4*)&sm.Qf[((mtile * 24 + ks) * 32 + lane) * 4];
#pragma unroll
                for (int j = 0; j < 4; j++) {
                    float2 bb = *(const float2*)&sm.Kf[(((ntb + j) * 24 + ks) * 32 + lane) * 2];
                    mma_tf32(c[j][0], c[j][1], c[j][2], c[j][3],
                             a.x, a.y, a.z, a.w, bb.x, bb.y);
                }
            }

            const bool diag = (kt >= 2 * qt);      // only last two k-tiles can mask
            const int r0 = mtile * 16 + qid;
#pragma unroll
            for (int j = 0; j < 4; j++) {
                int col = (ntb + j) * 8 + rid * 2;
                int ki0 = kt * BKT + col;
                float s0 = c[j][0] * SM_SCALE, s1 = c[j][1] * SM_SCALE;
                float s2 = c[j][2] * SM_SCALE, s3 = c[j][3] * SM_SCALE;
                if (diag) {
                    int qi0 = qt * BQ + r0;
                    int qi1 = qi0 + 8;
                    if (ki0     > qi0) s0 = -1e9f;
                    if (ki0 + 1 > qi0) s1 = -1e9f;
                    if (ki0     > qi1) s2 = -1e9f;
                    if (ki0 + 1 > qi1) s3 = -1e9f;
                }
                *(float2*)&sm.P[r0][col]     = make_float2(s0, s1);
                *(float2*)&sm.P[r0 + 8][col] = make_float2(s2, s3);
            }
        }
        __syncthreads();

        // ---- online softmax (l in fp32; P stored tf32 for the PV mma) ----
        {
            float sv[16];
            float tmax = -1e30f;
#pragma unroll
            for (int jj = 0; jj < 16; jj++) {
                sv[jj] = sm.P[srow][squad * 16 + jj];
                tmax = fmaxf(tmax, sv[jj]);
            }
            tmax = fmaxf(tmax, __shfl_xor_sync(0xffffffffu, tmax, 1));
            tmax = fmaxf(tmax, __shfl_xor_sync(0xffffffffu, tmax, 2));
            float mnew = fmaxf(m, tmax);
            float al   = __expf(m - mnew);
            float ps = 0.f;
#pragma unroll
            for (int jj = 0; jj < 16; jj++) {
                float p = __expf(sv[jj] - mnew);
                sm.P[srow][squad * 16 + jj] = to_tf32(p);
                ps += p;
            }
            ps += __shfl_xor_sync(0xffffffffu, ps, 1);
            ps += __shfl_xor_sync(0xffffffffu, ps, 2);
            l = l * al + ps;
            m = mnew;
            if (squad == 0) sm.alpha[srow] = al;
        }
        __syncthreads();

        // ---- O = O*alpha + P @ V via tf32 mma ----
        {
            const float al0 = sm.alpha[row0];
            const float al1 = sm.alpha[row0 + 8];
#pragma unroll
            for (int j = 0; j < 8; j++) {
                acc[j][0] *= al0; acc[j][1] *= al0;
                acc[j][2] *= al1; acc[j][3] *= al1;
            }
#pragma unroll
            for (int ks = 0; ks < 8; ks++) {
                const float a0 = sm.P[row0]    [ks * 8 + rid];
                const float a1 = sm.P[row0 + 8][ks * 8 + rid];
                const float a2 = sm.P[row0]    [ks * 8 + rid + 4];
                const float a3 = sm.P[row0 + 8][ks * 8 + rid + 4];
#pragma unroll
                for (int j = 0; j < 8; j++) {
                    const float b0 = sm.V[ks * 8 + rid]    [nbv + j * 8 + qid];
                    const float b1 = sm.V[ks * 8 + rid + 4][nbv + j * 8 + qid];
                    mma_tf32(acc[j][0], acc[j][1], acc[j][2], acc[j][3],
                             a0, a1, a2, a3, b0, b1);
                }
            }
        }
    }

    if (squad == 0) sm.invl[srow] = 1.f / l;
    __syncthreads();

    // ---- epilogue: scale by 1/l, write out (mma C layout) ----
    {
        const float il0 = sm.invl[row0];
        const float il1 = sm.invl[row0 + 8];
        const int tok0 = qb + row0;
        const int tok1 = tok0 + 8;
#pragma unroll
        for (int j = 0; j < 8; j++) {
            const int col = nbv + j * 8 + rid * 2;
            *(float2*)&out[(size_t)tok0 * (NH * VD) + h * VD + col] =
                make_float2(acc[j][0] * il0, acc[j][1] * il0);
            *(float2*)&out[(size_t)tok1 * (NH * VD) + h * VD + col] =
                make_float2(acc[j][2] * il1, acc[j][3] * il1);
        }
    }
}

// ---------------------------------------------------------------------------
// Launch
// ---------------------------------------------------------------------------
static void launch_gemm(const float* A, const float* B, float* C,
                        int M, int N, int K)
{
    dim3 grid((N + 127) / 128, (M + 127) / 128);
    tf32_gemm_kernel<<<grid, 256>>>(A, B, C, M, N, K);
}

extern "C" void kernel_launch(void* const* d_in, const int* in_sizes, int n_in,
                              void* d_out, int out_size)
{
    const float* x         = (const float*)d_in[0];
    const float* W_cq      = (const float*)d_in[1];
    const float* q_scale   = (const float*)d_in[2];
    const float* W_dq_nope = (const float*)d_in[3];
    const float* W_dq_rope = (const float*)d_in[4];
    const float* W_ckv     = (const float*)d_in[5];
    const float* kv_scale  = (const float*)d_in[6];
    const float* W_dk_nope = (const float*)d_in[7];
    const float* W_dv      = (const float*)d_in[8];
    const float* W_krope   = (const float*)d_in[9];
    const float* W_o       = (const float*)d_in[10];
    float* out = (float*)d_out;

    float *cq, *qn, *qr, *ckv, *kn, *vv, *kr, *att, *ctab, *stab;
    cudaGetSymbolAddress((void**)&cq,  g_cq);
    cudaGetSymbolAddress((void**)&qn,  g_qnope);
    cudaGetSymbolAddress((void**)&qr,  g_qrope);
    cudaGetSymbolAddress((void**)&ckv, g_ckv);
    cudaGetSymbolAddress((void**)&kn,  g_knope);
    cudaGetSymbolAddress((void**)&vv,  g_v);
    cudaGetSymbolAddress((void**)&kr,  g_krope);
    cudaGetSymbolAddress((void**)&att, g_attn);
    cudaGetSymbolAddress((void**)&ctab, g_ctab);
    cudaGetSymbolAddress((void**)&stab, g_stab);

    // RoPE tables
    rope_table_kernel<<<(S * 32 + 255) / 256, 256>>>(ctab, stab);

    // Q path
    launch_gemm(x, W_cq, cq, T, QR, H);
    rmsnorm_kernel<<<T, 256>>>(cq, q_scale, QR);
    launch_gemm(cq, W_dq_nope, qn, T, NH * NOPE, QR);
    launch_gemm(cq, W_dq_rope, qr, T, NH * ROPE, QR);
    rope_q_kernel<<<(T * NH * 32 + 255) / 256, 256>>>(qr, ctab, stab);

    // KV path
    launch_gemm(x, W_ckv, ckv, T, KVR, H);
    rmsnorm_kernel<<<T, 256>>>(ckv, kv_scale, KVR);
    launch_gemm(ckv, W_dk_nope, kn, T, NH * NOPE, KVR);
    launch_gemm(ckv, W_dv, vv, T, NH * VD, KVR);
    launch_gemm(x, W_krope, kr, T, ROPE, H);
    rope_k_kernel<<<(T * 32 + 255) / 256, 256>>>(kr, ctab, stab);

    // Attention
    cudaFuncSetAttribute((const void*)attn_kernel,
                         cudaFuncAttributeMaxDynamicSharedMemorySize,
                         (int)sizeof(AttnSmem));
    attn_kernel<<<dim3(S / BQ, NH, BB), 512, sizeof(AttnSmem)>>>(qn, qr, kn, kr, vv, att);

    // Output projection
    launch_gemm(att, W_o, out, T, H, NH * VD);
}